// round 7
// baseline (speedup 1.0000x reference)
#include <cuda_runtime.h>
#include <cuda_bf16.h>
#include <cstdint>
#include <math.h>

typedef unsigned int uint;
typedef unsigned long long ull;
typedef unsigned short ushort;

// ---------------------------------------------------------------------------
// Problem constants
// ---------------------------------------------------------------------------
#define BGR   16384
#define NPG   9
#define NNODE (BGR * NPG)      // 147456
#define DM    128
#define DFF   512
#define NL    4
#define EPG   16

#define NTILES (NNODE / 128)   // 1152

// smem tile geometry: 128 rows x 128 bf16, padded row stride 272 B (17x16B)
#define LDT_B   272
#define TILE_B  (128 * LDT_B)          // 34816

// fused layer kernel smem map (dynamic, 6 tiles = 208896 B):
//  H pair:  [0, 2T)        Wg (prefetch) -> LN'd h (resident through FFN)
//  S1 pair: [2T, 4T)       agg-A tiles -> W1 chunk -> mid tiles
//  S2 pair: [4T, 6T)       f32 stage (stride 132) / W2 chunk
//  transient (agg phase only):
//   hs  f32[144][128] at [2T, 2T+73728)
//   aggst f32[128][128] at [2T+73728, 6T)   (73728+65536 = 139264 = 4T exactly)
#define H_HI    0
#define H_LO    TILE_B
#define S1_HI   (2 * TILE_B)
#define S1_LO   (3 * TILE_B)
#define S2_HI   (4 * TILE_B)
#define S2_LO   (5 * TILE_B)
#define HS_O    (2 * TILE_B)
#define AGGST_O (2 * TILE_B + 73728)
#define STAGE_O (4 * TILE_B)
#define LK_SMEM (6 * TILE_B)           // 208896

// ---------------------------------------------------------------------------
// Scratch (device globals)
// h buffers: packed split bf16 (hi | lo<<16). Weights: separate hi/lo planes.
// ---------------------------------------------------------------------------
__device__ uint   g_hA[(size_t)NNODE * DM];
__device__ uint   g_hB[(size_t)NNODE * DM];
__device__ float  g_inv[NNODE];
__device__ ushort g_Wgh[(size_t)NL * DM * DM],  g_Wgl[(size_t)NL * DM * DM];
__device__ ushort g_W1h[(size_t)NL * DFF * DM], g_W1l[(size_t)NL * DFF * DM];
__device__ ushort g_W2h[(size_t)NL * DM * DFF], g_W2l[(size_t)NL * DM * DFF];

// ---------------------------------------------------------------------------
// helpers
// ---------------------------------------------------------------------------
__device__ __forceinline__ uint smem_u32(const void* p) {
    uint a;
    asm("{ .reg .u64 t; cvta.to.shared.u64 t, %1; cvt.u32.u64 %0, t; }" : "=r"(a) : "l"(p));
    return a;
}
__device__ __forceinline__ void ldsm4(uint* r, uint addr) {
    asm volatile("ldmatrix.sync.aligned.m8n8.x4.shared.b16 {%0,%1,%2,%3}, [%4];"
        : "=r"(r[0]), "=r"(r[1]), "=r"(r[2]), "=r"(r[3]) : "r"(addr));
}
__device__ __forceinline__ void mma_bf16(float* c, const uint* a, const uint* b) {
    asm volatile("mma.sync.aligned.m16n8k16.row.col.f32.bf16.bf16.f32 "
        "{%0,%1,%2,%3}, {%4,%5,%6,%7}, {%8,%9}, {%0,%1,%2,%3};"
        : "+f"(c[0]), "+f"(c[1]), "+f"(c[2]), "+f"(c[3])
        : "r"(a[0]), "r"(a[1]), "r"(a[2]), "r"(a[3]), "r"(b[0]), "r"(b[1]));
}
__device__ __forceinline__ uint pksplit(float v) {
    __nv_bfloat16 h = __float2bfloat16(v);
    __nv_bfloat16 l = __float2bfloat16(v - __bfloat162float(h));
    return (uint)__bfloat16_as_ushort(h) | ((uint)__bfloat16_as_ushort(l) << 16);
}
__device__ __forceinline__ float unpks(uint u) {
    return __bfloat162float(__ushort_as_bfloat16((ushort)(u & 0xffffu)))
         + __bfloat162float(__ushort_as_bfloat16((ushort)(u >> 16)));
}
__device__ __forceinline__ float bfu(uint s) {
    return __bfloat162float(__ushort_as_bfloat16((ushort)s));
}

#define CP16(sm, gp) do {                                                     \
    unsigned long long _g;                                                    \
    asm("cvta.to.global.u64 %0, %1;" : "=l"(_g) : "l"(gp));                   \
    asm volatile("cp.async.cg.shared.global [%0], [%1], 16;" :: "r"(sm), "l"(_g)); \
} while (0)
#define CP_COMMIT() asm volatile("cp.async.commit_group;" ::: "memory")
#define CP_WAIT(n)  asm volatile("cp.async.wait_group %0;" :: "n"(n) : "memory")

// async load of a 128x128 bf16 tile pair (hi+lo planes) into a pair base.
// 16 cp.async of 16B per thread (4096 total).
__device__ __forceinline__ void cpa_w_tile(const ushort* __restrict__ gh,
                                           const ushort* __restrict__ gl,
                                           int row0, int col0, int ldg,
                                           uint sbase, int tid) {
#pragma unroll
    for (int i = 0; i < 8; i++) {
        int idx = tid + 256 * i;       // 2048 granules per plane
        int r = idx >> 4, g = idx & 15;
        uint d = sbase + r * LDT_B + g * 16;
        CP16(d,          gh + (size_t)(row0 + r) * ldg + col0 + g * 8);
        CP16(d + TILE_B, gl + (size_t)(row0 + r) * ldg + col0 + g * 8);
    }
}

// ---------------------------------------------------------------------------
// MMA core: warp tile 32(M) x 64(N), K=128 chunk, 3-pass split accumulate
// ---------------------------------------------------------------------------
__device__ __forceinline__ void mma_chunk(uint aHi, uint aLo, uint bHi, uint bLo,
                                          const uint* offA, const uint* offB,
                                          float acc[2][8][4]) {
#pragma unroll
    for (int ks = 0; ks < 8; ks++) {
        uint kb = ks * 32;
        uint ah[2][4], al[2][4], bh[4][4], bl[4][4];
        ldsm4(ah[0], aHi + offA[0] + kb);
        ldsm4(ah[1], aHi + offA[1] + kb);
        ldsm4(al[0], aLo + offA[0] + kb);
        ldsm4(al[1], aLo + offA[1] + kb);
#pragma unroll
        for (int p = 0; p < 4; p++) {
            ldsm4(bh[p], bHi + offB[p] + kb);
            ldsm4(bl[p], bLo + offB[p] + kb);
        }
#pragma unroll
        for (int im = 0; im < 2; im++)
#pragma unroll
            for (int p = 0; p < 4; p++) {
                mma_bf16(acc[im][2 * p],     ah[im], &bh[p][0]);
                mma_bf16(acc[im][2 * p + 1], ah[im], &bh[p][2]);
                mma_bf16(acc[im][2 * p],     ah[im], &bl[p][0]);
                mma_bf16(acc[im][2 * p + 1], ah[im], &bl[p][2]);
                mma_bf16(acc[im][2 * p],     al[im], &bh[p][0]);
                mma_bf16(acc[im][2 * p + 1], al[im], &bh[p][2]);
            }
    }
}

__device__ __forceinline__ void zero_acc(float acc[2][8][4]) {
#pragma unroll
    for (int im = 0; im < 2; im++)
#pragma unroll
        for (int in = 0; in < 8; in++)
#pragma unroll
            for (int r = 0; r < 4; r++) acc[im][in][r] = 0.f;
}

__device__ __forceinline__ void make_offs(int lane, int wm, int wn,
                                          uint* offA, uint* offB) {
#pragma unroll
    for (int im = 0; im < 2; im++)
        offA[im] = (uint)((wm * 32 + im * 16 + (lane & 15)) * LDT_B + ((lane >> 4) << 4));
#pragma unroll
    for (int p = 0; p < 4; p++)
        offB[p] = (uint)((wn * 64 + p * 16 + (lane & 7) + ((lane >> 4) << 3)) * LDT_B
                         + (((lane >> 3) & 1) << 4));
}

// stage acc (raw) into f32 smem [128][132]
__device__ __forceinline__ void stage_acc(float* st, int wm, int wn, int lane,
                                          float acc[2][8][4]) {
    int gid = lane >> 2, tig = lane & 3;
#pragma unroll
    for (int im = 0; im < 2; im++)
#pragma unroll
        for (int in = 0; in < 8; in++)
#pragma unroll
            for (int r = 0; r < 4; r++) {
                int row = wm * 32 + im * 16 + gid + 8 * (r >> 1);
                int col = wn * 64 + in * 8 + 2 * tig + (r & 1);
                st[row * 132 + col] = acc[im][in][r];
            }
}

// ---------------------------------------------------------------------------
// K0: degree -> inv_sqrt_deg
// ---------------------------------------------------------------------------
__global__ void deg_kernel(const int* __restrict__ dst) {
    int g = blockIdx.x * blockDim.x + threadIdx.x;
    if (g >= BGR) return;
    int base = g * NPG;
    int cnt[NPG];
#pragma unroll
    for (int j = 0; j < NPG; j++) cnt[j] = 1;
#pragma unroll
    for (int e = 0; e < EPG; e++) {
        int dl = dst[g * EPG + e] - base;
#pragma unroll
        for (int j = 0; j < NPG; j++) cnt[j] += (dl == j) ? 1 : 0;
    }
#pragma unroll
    for (int j = 0; j < NPG; j++)
        g_inv[base + j] = rsqrtf((float)cnt[j]);
}

// ---------------------------------------------------------------------------
// K1: embedding -> g_hA packed split
// ---------------------------------------------------------------------------
__global__ void embed_kernel(const float4* __restrict__ opt,
                             const float4* __restrict__ de,
                             const int* __restrict__ op_idx) {
    int idx = blockIdx.x * blockDim.x + threadIdx.x;   // NNODE*32
    int n = idx >> 5, c = idx & 31;
    float4 t = opt[op_idx[n] * 32 + c];
    float4 d = de[c];
    uint4 o = make_uint4(pksplit(t.x + d.x), pksplit(t.y + d.y),
                         pksplit(t.z + d.z), pksplit(t.w + d.w));
    reinterpret_cast<uint4*>(g_hA)[idx] = o;
}

// ---------------------------------------------------------------------------
// Weight prep: planes[c][r] = split(src[r][c])
// ---------------------------------------------------------------------------
__global__ void prep_w(const float* __restrict__ src,
                       ushort* __restrict__ dh, ushort* __restrict__ dl,
                       int R, int C) {
    int l = blockIdx.z;
    src += (size_t)l * R * C;
    dh  += (size_t)l * R * C;
    dl  += (size_t)l * R * C;
    int n = blockIdx.x * blockDim.x + threadIdx.x;
    if (n >= R * C) return;
    int c = n / R, r = n % R;
    uint u = pksplit(src[(size_t)r * C + c]);
    dh[n] = (ushort)(u & 0xffffu);
    dl[n] = (ushort)(u >> 16);
}

// ---------------------------------------------------------------------------
// Fused layer kernel: agg -> GCN mma -> LN -> FFN(4 chunks) -> residual
// ---------------------------------------------------------------------------
__global__ __launch_bounds__(256) void layer_kernel(
    const uint* __restrict__ h_in, uint* __restrict__ h_out,
    const ushort* __restrict__ Wgh, const ushort* __restrict__ Wgl,
    const ushort* __restrict__ W1h, const ushort* __restrict__ W1l,
    const ushort* __restrict__ W2h, const ushort* __restrict__ W2l,
    const float* __restrict__ bg, const float* __restrict__ lng,
    const float* __restrict__ lnb, const float* __restrict__ b1,
    const float* __restrict__ b2,
    const int* __restrict__ src, const int* __restrict__ dst) {

    extern __shared__ char dsm[];
    __shared__ __align__(16) float sBg[DM], sLng[DM], sLnb[DM], sB1[DFF], sB2[DM];
    __shared__ float sinv[144];
    __shared__ short ssl[256], sdl[256];

    int tid = threadIdx.x, lane = tid & 31, wid = tid >> 5;
    int wm = wid & 3, wn = wid >> 2;
    uint sb = smem_u32(dsm);
    int m0 = blockIdx.x * 128;

    // graphs overlapping this tile
    int G0 = m0 / NPG;
    int G1 = (m0 + 127) / NPG;
    int nG = G1 - G0 + 1;                // <= 16
    int nb = G0 * NPG;                   // first node loaded
    int mo = nb - m0;                    // in (-9, 0]
    int cnt = nG * NPG;                  // rows of hs, <= 144

    // P0: prefetch Wg into H pair (async) --------------------------------
    cpa_w_tile(Wgh, Wgl, 0, 0, DM, sb + H_HI, tid);
    CP_COMMIT();

    // biases / LN params / edge data
    if (tid < DM) { sBg[tid] = bg[tid]; sLng[tid] = lng[tid]; sLnb[tid] = lnb[tid]; sB2[tid] = b2[tid]; }
    for (int i = tid; i < DFF; i += 256) sB1[i] = b1[i];
    if (tid < nG * EPG) {
        ssl[tid] = (short)(src[G0 * EPG + tid] - nb);
        sdl[tid] = (short)(dst[G0 * EPG + tid] - nb);
    }
    if (tid < cnt) sinv[tid] = g_inv[nb + tid];

    // P1: load h rows (packed) -> hs f32 ---------------------------------
    float* hs = (float*)(dsm + HS_O);
    {
        int tot4 = cnt * 32;             // uint4 count, <= 4608
#pragma unroll
        for (int i = 0; i < 18; i++) {
            int idx = tid + 256 * i;
            if (idx < tot4) {
                int r = idx >> 5, q = idx & 31;
                uint4 u = *reinterpret_cast<const uint4*>(h_in + (size_t)(nb + r) * DM + 4 * q);
                float* p = hs + r * 128 + 4 * q;
                p[0] = unpks(u.x); p[1] = unpks(u.y); p[2] = unpks(u.z); p[3] = unpks(u.w);
            }
        }
    }
    __syncthreads();

    // P2: aggregation into aggst f32[128][128] ---------------------------
    float* aggst = (float*)(dsm + AGGST_O);
    {
        int col = tid & 127;
        for (int lg = (tid >> 7); lg < nG; lg += 2) {
            int rb = NPG * lg;
#pragma unroll
            for (int j = 0; j < NPG; j++) {
                int tr = rb + j + mo;
                if (0 <= tr && tr < 128) {
                    float iv = sinv[rb + j];
                    aggst[tr * 128 + col] = iv * iv * hs[(rb + j) * 128 + col];
                }
            }
#pragma unroll
            for (int e = 0; e < EPG; e++) {
                int i = lg * EPG + e;
                int dl = sdl[i], sl = ssl[i];
                int tr = dl + mo;
                if (0 <= tr && tr < 128) {
                    float w = sinv[sl] * sinv[dl];
                    aggst[tr * 128 + col] += w * hs[sl * 128 + col];
                }
            }
        }
    }
    __syncthreads();

    // P3: split aggst -> A tiles in S1 (hs dead) -------------------------
    {
#pragma unroll
        for (int i = 0; i < 64; i++) {
            int idx = tid + 256 * i;     // 16384
            int r = idx >> 7, c = idx & 127;
            uint u = pksplit(aggst[idx]);
            *reinterpret_cast<ushort*>(dsm + S1_HI + r * LDT_B + c * 2) = (ushort)(u & 0xffffu);
            *reinterpret_cast<ushort*>(dsm + S1_LO + r * LDT_B + c * 2) = (ushort)(u >> 16);
        }
    }
    __syncthreads();

    uint offA[2], offB[4];
    make_offs(lane, wm, wn, offA, offB);

    // P4: GCN mma  (A = S1, B = Wg in H) ---------------------------------
    CP_WAIT(0);
    __syncthreads();
    float acc[2][8][4];
    zero_acc(acc);
    mma_chunk(sb + S1_HI, sb + S1_LO, sb + H_HI, sb + H_LO, offA, offB, acc);
    __syncthreads();                     // S1 + H(Wg) free

    // P5: prefetch W1 chunk0 into S1 (async), stage + LN -> H pair -------
    cpa_w_tile(W1h, W1l, 0, 0, DM, sb + S1_HI, tid);
    CP_COMMIT();

    float* stage = (float*)(dsm + STAGE_O);
    stage_acc(stage, wm, wn, lane, acc);
    __syncthreads();
    {
        float4 gq = *reinterpret_cast<const float4*>(&sLng[lane * 4]);
        float4 bq = *reinterpret_cast<const float4*>(&sLnb[lane * 4]);
        float4 bb = *reinterpret_cast<const float4*>(&sBg[lane * 4]);
        for (int it = 0; it < 16; it++) {
            int r = wid * 16 + it;
            float4 x = *reinterpret_cast<const float4*>(&stage[r * 132 + lane * 4]);
            x.x = fmaxf(x.x + bb.x, 0.f); x.y = fmaxf(x.y + bb.y, 0.f);
            x.z = fmaxf(x.z + bb.z, 0.f); x.w = fmaxf(x.w + bb.w, 0.f);
            float s = x.x + x.y + x.z + x.w;
#pragma unroll
            for (int o = 16; o; o >>= 1) s += __shfl_xor_sync(0xffffffffu, s, o);
            float mu = s * (1.f / 128.f);
            float dx = x.x - mu, dy = x.y - mu, dz = x.z - mu, dw = x.w - mu;
            float q = dx * dx + dy * dy + dz * dz + dw * dw;
#pragma unroll
            for (int o = 16; o; o >>= 1) q += __shfl_xor_sync(0xffffffffu, q, o);
            float rs = rsqrtf(q * (1.f / 128.f) + 1e-5f);
            uint u0 = pksplit(dx * rs * gq.x + bq.x);
            uint u1 = pksplit(dy * rs * gq.y + bq.y);
            uint u2 = pksplit(dz * rs * gq.z + bq.z);
            uint u3 = pksplit(dw * rs * gq.w + bq.w);
            uint2 hh = make_uint2((u0 & 0xffffu) | (u1 << 16), (u2 & 0xffffu) | (u3 << 16));
            uint2 hl = make_uint2((u0 >> 16) | (u1 & 0xffff0000u), (u2 >> 16) | (u3 & 0xffff0000u));
            *reinterpret_cast<uint2*>(dsm + H_HI + r * LDT_B + lane * 8) = hh;
            *reinterpret_cast<uint2*>(dsm + H_LO + r * LDT_B + lane * 8) = hl;
        }
    }
    __syncthreads();                     // H = LN'd h; S2 stage dead

    // P6: FFN loop -------------------------------------------------------
    int gid = lane >> 2, tig = lane & 3;
    float acc2[2][8][4];
    zero_acc(acc2);
    for (int c = 0; c < 4; c++) {
        // prefetch W2 chunk c into S2 (overlaps mma1)
        cpa_w_tile(W2h, W2l, 0, c * 128, DFF, sb + S2_HI, tid);
        CP_COMMIT();
        CP_WAIT(1);                      // W1c ready (W2c still pending)
        __syncthreads();

        float acc1[2][8][4];
        zero_acc(acc1);
        mma_chunk(sb + H_HI, sb + H_LO, sb + S1_HI, sb + S1_LO, offA, offB, acc1);
        __syncthreads();                 // S1 (W1c) free

        // relu + bias -> split mid into S1
#pragma unroll
        for (int im = 0; im < 2; im++)
#pragma unroll
            for (int in = 0; in < 8; in++)
#pragma unroll
                for (int r = 0; r < 4; r++) {
                    int row = wm * 32 + im * 16 + gid + 8 * (r >> 1);
                    int col = wn * 64 + in * 8 + 2 * tig + (r & 1);
                    float v = fmaxf(acc1[im][in][r] + sB1[c * 128 + col], 0.f);
                    uint u = pksplit(v);
                    *reinterpret_cast<ushort*>(dsm + S1_HI + row * LDT_B + col * 2) =
                        (ushort)(u & 0xffffu);
                    *reinterpret_cast<ushort*>(dsm + S1_LO + row * LDT_B + col * 2) =
                        (ushort)(u >> 16);
                }
        CP_WAIT(0);                      // W2c ready
        __syncthreads();                 // mid visible

        mma_chunk(sb + S1_HI, sb + S1_LO, sb + S2_HI, sb + S2_LO, offA, offB, acc2);
        __syncthreads();                 // S1, S2 free

        if (c < 3) {
            cpa_w_tile(W1h, W1l, (c + 1) * 128, 0, DM, sb + S1_HI, tid);
            CP_COMMIT();
        }
    }

    // P7: epilogue  h_out = h + ffn_out + b2 -----------------------------
    stage_acc(stage, wm, wn, lane, acc2);
    __syncthreads();
#pragma unroll
    for (int i = 0; i < 16; i++) {
        int idx = tid + 256 * i;
        int r = idx >> 5, q = idx & 31;
        float4 v = *reinterpret_cast<const float4*>(&stage[r * 132 + 4 * q]);
        uint2 hh = *reinterpret_cast<const uint2*>(dsm + H_HI + r * LDT_B + 8 * q);
        uint2 hl = *reinterpret_cast<const uint2*>(dsm + H_LO + r * LDT_B + 8 * q);
        float h0 = bfu(hh.x & 0xffffu) + bfu(hl.x & 0xffffu);
        float h1 = bfu(hh.x >> 16)     + bfu(hl.x >> 16);
        float h2 = bfu(hh.y & 0xffffu) + bfu(hl.y & 0xffffu);
        float h3 = bfu(hh.y >> 16)     + bfu(hl.y >> 16);
        uint4 o = make_uint4(pksplit(v.x + sB2[4 * q]     + h0),
                             pksplit(v.y + sB2[4 * q + 1] + h1),
                             pksplit(v.z + sB2[4 * q + 2] + h2),
                             pksplit(v.w + sB2[4 * q + 3] + h3));
        *reinterpret_cast<uint4*>(h_out + (size_t)(m0 + r) * DM + 4 * q) = o;
    }
}

// ---------------------------------------------------------------------------
// K6: readout (reads g_hA — final parity after 4 layers)
// ---------------------------------------------------------------------------
__global__ __launch_bounds__(128) void readout_kernel(const float4* __restrict__ fcw,
                                                      const float* __restrict__ fcb,
                                                      float* __restrict__ out) {
    int w = threadIdx.x >> 5, lane = threadIdx.x & 31;
    int g = blockIdx.x * 4 + w;
    const uint4* h4 = reinterpret_cast<const uint4*>(g_hA);
    size_t base = (size_t)g * NPG * 32;
    float4 s = make_float4(0.f, 0.f, 0.f, 0.f);
#pragma unroll
    for (int j = 0; j < NPG; j++) {
        uint4 v = h4[base + j * 32 + lane];
        s.x += unpks(v.x); s.y += unpks(v.y); s.z += unpks(v.z); s.w += unpks(v.w);
    }
    float4 wv = fcw[lane];
    float p = s.x * wv.x + s.y * wv.y + s.z * wv.z + s.w * wv.w;
#pragma unroll
    for (int o = 16; o; o >>= 1) p += __shfl_xor_sync(0xffffffffu, p, o);
    if (lane == 0)
        out[g] = 1.f / (1.f + expf(-(p * (1.f / 9.f) + fcb[0])));
}

// ---------------------------------------------------------------------------
// Launcher
// ---------------------------------------------------------------------------
extern "C" void kernel_launch(void* const* d_in, const int* in_sizes, int n_in,
                              void* d_out, int out_size) {
    const float* op_table   = (const float*)d_in[0];
    const float* device_emb = (const float*)d_in[1];
    const float* Wg         = (const float*)d_in[2];
    const float* bg         = (const float*)d_in[3];
    const float* ln_g       = (const float*)d_in[4];
    const float* ln_b       = (const float*)d_in[5];
    const float* W1         = (const float*)d_in[6];
    const float* b1         = (const float*)d_in[7];
    const float* W2         = (const float*)d_in[8];
    const float* b2         = (const float*)d_in[9];
    const float* fc_w       = (const float*)d_in[10];
    const float* fc_b       = (const float*)d_in[11];
    const int*   op_idx     = (const int*)d_in[12];
    const int*   src        = (const int*)d_in[13];
    const int*   dst        = (const int*)d_in[14];
    float* out = (float*)d_out;

    cudaFuncSetAttribute(layer_kernel, cudaFuncAttributeMaxDynamicSharedMemorySize, LK_SMEM);

    uint *hA, *hB;
    ushort *wgh, *wgl, *w1h, *w1l, *w2h, *w2l;
    cudaGetSymbolAddress((void**)&hA, g_hA);
    cudaGetSymbolAddress((void**)&hB, g_hB);
    cudaGetSymbolAddress((void**)&wgh, g_Wgh);
    cudaGetSymbolAddress((void**)&wgl, g_Wgl);
    cudaGetSymbolAddress((void**)&w1h, g_W1h);
    cudaGetSymbolAddress((void**)&w1l, g_W1l);
    cudaGetSymbolAddress((void**)&w2h, g_W2h);
    cudaGetSymbolAddress((void**)&w2l, g_W2l);

    prep_w<<<dim3((DM * DM + 255) / 256, 1, NL), 256>>>(Wg, wgh, wgl, DM, DM);
    prep_w<<<dim3((DM * DFF + 255) / 256, 1, NL), 256>>>(W1, w1h, w1l, DM, DFF);
    prep_w<<<dim3((DM * DFF + 255) / 256, 1, NL), 256>>>(W2, w2h, w2l, DFF, DM);

    deg_kernel<<<BGR / 256, 256>>>(dst);
    embed_kernel<<<(NNODE * 32) / 256, 256>>>(
        (const float4*)op_table, (const float4*)device_emb, op_idx);

    for (int l = 0; l < NL; l++) {
        const uint* hin = (l & 1) ? hB : hA;
        uint*       hout = (l & 1) ? hA : hB;
        size_t o1 = (size_t)l * DM * DM, o2 = (size_t)l * DFF * DM, o3 = (size_t)l * DM * DFF;
        layer_kernel<<<NTILES, 256, LK_SMEM>>>(
            hin, hout,
            wgh + o1, wgl + o1, w1h + o2, w1l + o2, w2h + o3, w2l + o3,
            bg + l * DM, ln_g + l * DM, ln_b + l * DM, b1 + l * DFF, b2 + l * DM,
            src, dst);
    }

    readout_kernel<<<BGR / 4, 128>>>((const float4*)fc_w, fc_b, out);
}

// round 8
// speedup vs baseline: 1.2221x; 1.2221x over previous
#include <cuda_runtime.h>
#include <cuda_bf16.h>
#include <cstdint>
#include <math.h>

typedef unsigned int uint;
typedef unsigned long long ull;
typedef unsigned short ushort;

// ---------------------------------------------------------------------------
// Problem constants
// ---------------------------------------------------------------------------
#define BGR   16384
#define NPG   9
#define NNODE (BGR * NPG)      // 147456
#define DM    128
#define DFF   512
#define NL    4
#define EPG   16

#define NTILES (NNODE / 128)   // 1152

// smem tile geometry: 128 rows x 128 bf16, padded row stride 272 B (17x16B)
#define LDT_B   272
#define TILE_B  (128 * LDT_B)          // 34816

// gcn layout: A pair [0,2T), B pair [2T,4T), f32 stage reuses A region
#define A_HI    0
#define A_LO    TILE_B
#define B_HI    (2 * TILE_B)
#define B_LO    (3 * TILE_B)
#define GM_SMEM (4 * TILE_B)           // 139264

// ffn layout: H pair, S1 pair (W1/mid), S2 pair (W2/stage)
#define H_HI    0
#define H_LO    TILE_B
#define S1_HI   (2 * TILE_B)
#define S1_LO   (3 * TILE_B)
#define S2_HI   (4 * TILE_B)
#define S2_LO   (5 * TILE_B)
#define STAGE_O (4 * TILE_B)
#define FF_SMEM (6 * TILE_B)           // 208896

// ---------------------------------------------------------------------------
// Scratch (device globals) — activations and weights as separate hi/lo
// bf16 planes; value = hi + lo.
// ---------------------------------------------------------------------------
__device__ ushort g_hh [(size_t)NNODE * DM], g_hl [(size_t)NNODE * DM];
__device__ ushort g_agh[(size_t)NNODE * DM], g_agl[(size_t)NNODE * DM];
__device__ float  g_inv[NNODE];
__device__ ushort g_Wgh[(size_t)NL * DM * DM],  g_Wgl[(size_t)NL * DM * DM];
__device__ ushort g_W1h[(size_t)NL * DFF * DM], g_W1l[(size_t)NL * DFF * DM];
__device__ ushort g_W2h[(size_t)NL * DM * DFF], g_W2l[(size_t)NL * DM * DFF];

// ---------------------------------------------------------------------------
// helpers
// ---------------------------------------------------------------------------
__device__ __forceinline__ uint smem_u32(const void* p) {
    uint a;
    asm("{ .reg .u64 t; cvta.to.shared.u64 t, %1; cvt.u32.u64 %0, t; }" : "=r"(a) : "l"(p));
    return a;
}
__device__ __forceinline__ void ldsm4(uint* r, uint addr) {
    asm volatile("ldmatrix.sync.aligned.m8n8.x4.shared.b16 {%0,%1,%2,%3}, [%4];"
        : "=r"(r[0]), "=r"(r[1]), "=r"(r[2]), "=r"(r[3]) : "r"(addr));
}
__device__ __forceinline__ void mma_bf16(float* c, const uint* a, const uint* b) {
    asm volatile("mma.sync.aligned.m16n8k16.row.col.f32.bf16.bf16.f32 "
        "{%0,%1,%2,%3}, {%4,%5,%6,%7}, {%8,%9}, {%0,%1,%2,%3};"
        : "+f"(c[0]), "+f"(c[1]), "+f"(c[2]), "+f"(c[3])
        : "r"(a[0]), "r"(a[1]), "r"(a[2]), "r"(a[3]), "r"(b[0]), "r"(b[1]));
}
__device__ __forceinline__ uint pksplit(float v) {
    __nv_bfloat16 h = __float2bfloat16(v);
    __nv_bfloat16 l = __float2bfloat16(v - __bfloat162float(h));
    return (uint)__bfloat16_as_ushort(h) | ((uint)__bfloat16_as_ushort(l) << 16);
}
__device__ __forceinline__ float bfu(uint s) {
    return __bfloat162float(__ushort_as_bfloat16((ushort)s));
}

#define CP16(sm, gp) do {                                                     \
    unsigned long long _g;                                                    \
    asm("cvta.to.global.u64 %0, %1;" : "=l"(_g) : "l"(gp));                   \
    asm volatile("cp.async.cg.shared.global [%0], [%1], 16;" :: "r"(sm), "l"(_g)); \
} while (0)
#define CP_COMMIT() asm volatile("cp.async.commit_group;" ::: "memory")
#define CP_WAIT(n)  asm volatile("cp.async.wait_group %0;" :: "n"(n) : "memory")

// async load of a 128x128 bf16 plane pair into (sbase, sbase+TILE_B).
// 4096 x 16B cp.async total across 256 threads.
__device__ __forceinline__ void cpa_tile(const ushort* __restrict__ gh,
                                         const ushort* __restrict__ gl,
                                         int row0, int col0, int ldg,
                                         uint sbase, int tid) {
#pragma unroll
    for (int i = 0; i < 8; i++) {
        int idx = tid + 256 * i;       // 2048 granules per plane
        int r = idx >> 4, g = idx & 15;
        uint d = sbase + r * LDT_B + g * 16;
        CP16(d,          gh + (size_t)(row0 + r) * ldg + col0 + g * 8);
        CP16(d + TILE_B, gl + (size_t)(row0 + r) * ldg + col0 + g * 8);
    }
}

// ---------------------------------------------------------------------------
// MMA core: warp tile 32(M) x 64(N), K=128 chunk, 3-pass split accumulate
// ---------------------------------------------------------------------------
__device__ __forceinline__ void mma_chunk(uint aHi, uint aLo, uint bHi, uint bLo,
                                          const uint* offA, const uint* offB,
                                          float acc[2][8][4]) {
#pragma unroll
    for (int ks = 0; ks < 8; ks++) {
        uint kb = ks * 32;
        uint ah[2][4], al[2][4], bh[4][4], bl[4][4];
        ldsm4(ah[0], aHi + offA[0] + kb);
        ldsm4(ah[1], aHi + offA[1] + kb);
        ldsm4(al[0], aLo + offA[0] + kb);
        ldsm4(al[1], aLo + offA[1] + kb);
#pragma unroll
        for (int p = 0; p < 4; p++) {
            ldsm4(bh[p], bHi + offB[p] + kb);
            ldsm4(bl[p], bLo + offB[p] + kb);
        }
#pragma unroll
        for (int im = 0; im < 2; im++)
#pragma unroll
            for (int p = 0; p < 4; p++) {
                mma_bf16(acc[im][2 * p],     ah[im], &bh[p][0]);
                mma_bf16(acc[im][2 * p + 1], ah[im], &bh[p][2]);
                mma_bf16(acc[im][2 * p],     ah[im], &bl[p][0]);
                mma_bf16(acc[im][2 * p + 1], ah[im], &bl[p][2]);
                mma_bf16(acc[im][2 * p],     al[im], &bh[p][0]);
                mma_bf16(acc[im][2 * p + 1], al[im], &bh[p][2]);
            }
    }
}

__device__ __forceinline__ void zero_acc(float acc[2][8][4]) {
#pragma unroll
    for (int im = 0; im < 2; im++)
#pragma unroll
        for (int in = 0; in < 8; in++)
#pragma unroll
            for (int r = 0; r < 4; r++) acc[im][in][r] = 0.f;
}

__device__ __forceinline__ void make_offs(int lane, int wm, int wn,
                                          uint* offA, uint* offB) {
#pragma unroll
    for (int im = 0; im < 2; im++)
        offA[im] = (uint)((wm * 32 + im * 16 + (lane & 15)) * LDT_B + ((lane >> 4) << 4));
#pragma unroll
    for (int p = 0; p < 4; p++)
        offB[p] = (uint)((wn * 64 + p * 16 + (lane & 7) + ((lane >> 4) << 3)) * LDT_B
                         + (((lane >> 3) & 1) << 4));
}

// stage acc (raw) into f32 smem [128][132]
__device__ __forceinline__ void stage_acc(float* st, int wm, int wn, int lane,
                                          float acc[2][8][4]) {
    int gid = lane >> 2, tig = lane & 3;
#pragma unroll
    for (int im = 0; im < 2; im++)
#pragma unroll
        for (int in = 0; in < 8; in++)
#pragma unroll
            for (int r = 0; r < 4; r++) {
                int row = wm * 32 + im * 16 + gid + 8 * (r >> 1);
                int col = wn * 64 + in * 8 + 2 * tig + (r & 1);
                st[row * 132 + col] = acc[im][in][r];
            }
}

// ---------------------------------------------------------------------------
// K0: degree -> inv_sqrt_deg
// ---------------------------------------------------------------------------
__global__ void deg_kernel(const int* __restrict__ dst) {
    int g = blockIdx.x * blockDim.x + threadIdx.x;
    if (g >= BGR) return;
    int base = g * NPG;
    int cnt[NPG];
#pragma unroll
    for (int j = 0; j < NPG; j++) cnt[j] = 1;
#pragma unroll
    for (int e = 0; e < EPG; e++) {
        int dl = dst[g * EPG + e] - base;
#pragma unroll
        for (int j = 0; j < NPG; j++) cnt[j] += (dl == j) ? 1 : 0;
    }
#pragma unroll
    for (int j = 0; j < NPG; j++)
        g_inv[base + j] = rsqrtf((float)cnt[j]);
}

// ---------------------------------------------------------------------------
// K1: embedding -> h planes
// ---------------------------------------------------------------------------
__global__ void embed_kernel(const float4* __restrict__ opt,
                             const float4* __restrict__ de,
                             const int* __restrict__ op_idx) {
    int idx = blockIdx.x * blockDim.x + threadIdx.x;   // NNODE*32
    int n = idx >> 5, c = idx & 31;
    float4 t = opt[op_idx[n] * 32 + c];
    float4 d = de[c];
    uint u0 = pksplit(t.x + d.x), u1 = pksplit(t.y + d.y);
    uint u2 = pksplit(t.z + d.z), u3 = pksplit(t.w + d.w);
    size_t o = (size_t)n * DM + 4 * c;
    *reinterpret_cast<ushort4*>(g_hh + o) =
        make_ushort4((ushort)u0, (ushort)u1, (ushort)u2, (ushort)u3);
    *reinterpret_cast<ushort4*>(g_hl + o) =
        make_ushort4((ushort)(u0 >> 16), (ushort)(u1 >> 16),
                     (ushort)(u2 >> 16), (ushort)(u3 >> 16));
}

// ---------------------------------------------------------------------------
// K2: per-graph aggregation (planes in / planes out, no atomics)
// ---------------------------------------------------------------------------
__global__ __launch_bounds__(128) void agg_kernel(const int* __restrict__ src,
                                                  const int* __restrict__ dst) {
    __shared__ float hs[NPG * DM];
    __shared__ float ag[NPG * DM];
    __shared__ float invs[NPG];
    __shared__ float we[EPG];
    __shared__ int sl[EPG], dl[EPG];

    int g = blockIdx.x, t = threadIdx.x;
    int nbase = g * NPG;
    if (t < NPG) invs[t] = g_inv[nbase + t];
    if (t < EPG) {
        sl[t] = src[g * EPG + t] - nbase;
        dl[t] = dst[g * EPG + t] - nbase;
    }
    __syncthreads();
    if (t < EPG) we[t] = invs[sl[t]] * invs[dl[t]];
#pragma unroll
    for (int j = 0; j < NPG; j++) {
        size_t o = (size_t)(nbase + j) * DM + t;
        float v = bfu(g_hh[o]) + bfu(g_hl[o]);
        hs[j * DM + t] = v;
        ag[j * DM + t] = invs[j] * invs[j] * v;
    }
    __syncthreads();
#pragma unroll
    for (int e = 0; e < EPG; e++)
        ag[dl[e] * DM + t] += we[e] * hs[sl[e] * DM + t];
#pragma unroll
    for (int j = 0; j < NPG; j++) {
        uint u = pksplit(ag[j * DM + t]);
        size_t o = (size_t)(nbase + j) * DM + t;
        g_agh[o] = (ushort)(u & 0xffffu);
        g_agl[o] = (ushort)(u >> 16);
    }
}

// ---------------------------------------------------------------------------
// Weight prep: planes[c][r] = split(src[r][c])
// ---------------------------------------------------------------------------
__global__ void prep_w(const float* __restrict__ src,
                       ushort* __restrict__ dh, ushort* __restrict__ dl,
                       int R, int C) {
    int l = blockIdx.z;
    src += (size_t)l * R * C;
    dh  += (size_t)l * R * C;
    dl  += (size_t)l * R * C;
    int n = blockIdx.x * blockDim.x + threadIdx.x;
    if (n >= R * C) return;
    int c = n / R, r = n % R;
    uint u = pksplit(src[(size_t)r * C + c]);
    dh[n] = (ushort)(u & 0xffffu);
    dl[n] = (ushort)(u >> 16);
}

// ---------------------------------------------------------------------------
// K3: GCN  h = LN(relu(agg @ Wg + bg))   (async A + Wg loads)
// ---------------------------------------------------------------------------
__global__ __launch_bounds__(256) void gcn_mma(const ushort* __restrict__ Wgh,
                                               const ushort* __restrict__ Wgl,
                                               const float* __restrict__ bg,
                                               const float* __restrict__ lng,
                                               const float* __restrict__ lnb) {
    extern __shared__ char dsm[];
    __shared__ __align__(16) float sBg[DM], sLng[DM], sLnb[DM];

    int tid = threadIdx.x, lane = tid & 31, wid = tid >> 5;
    int wm = wid & 3, wn = wid >> 2;
    uint sb = smem_u32(dsm);
    int m0 = blockIdx.x * 128;

    cpa_tile(g_agh + (size_t)m0 * DM, g_agl + (size_t)m0 * DM, 0, 0, DM, sb + A_HI, tid);
    cpa_tile(Wgh, Wgl, 0, 0, DM, sb + B_HI, tid);
    CP_COMMIT();

    if (tid < DM) { sBg[tid] = bg[tid]; sLng[tid] = lng[tid]; sLnb[tid] = lnb[tid]; }
    uint offA[2], offB[4];
    make_offs(lane, wm, wn, offA, offB);
    float acc[2][8][4];
    zero_acc(acc);

    CP_WAIT(0);
    __syncthreads();
    mma_chunk(sb + A_HI, sb + A_LO, sb + B_HI, sb + B_LO, offA, offB, acc);
    __syncthreads();
    float* stage = (float*)(dsm + A_HI);           // A pair dead
    stage_acc(stage, wm, wn, lane, acc);
    __syncthreads();

    float4 gq = *reinterpret_cast<const float4*>(&sLng[lane * 4]);
    float4 bq = *reinterpret_cast<const float4*>(&sLnb[lane * 4]);
    float4 bb = *reinterpret_cast<const float4*>(&sBg[lane * 4]);
    for (int it = 0; it < 16; it++) {
        int r = wid * 16 + it;
        float4 x = *reinterpret_cast<const float4*>(&stage[r * 132 + lane * 4]);
        x.x = fmaxf(x.x + bb.x, 0.f); x.y = fmaxf(x.y + bb.y, 0.f);
        x.z = fmaxf(x.z + bb.z, 0.f); x.w = fmaxf(x.w + bb.w, 0.f);
        float s = x.x + x.y + x.z + x.w;
#pragma unroll
        for (int o = 16; o; o >>= 1) s += __shfl_xor_sync(0xffffffffu, s, o);
        float mu = s * (1.f / 128.f);
        float dx = x.x - mu, dy = x.y - mu, dz = x.z - mu, dw = x.w - mu;
        float q = dx * dx + dy * dy + dz * dz + dw * dw;
#pragma unroll
        for (int o = 16; o; o >>= 1) q += __shfl_xor_sync(0xffffffffu, q, o);
        float rs = rsqrtf(q * (1.f / 128.f) + 1e-5f);
        uint u0 = pksplit(dx * rs * gq.x + bq.x);
        uint u1 = pksplit(dy * rs * gq.y + bq.y);
        uint u2 = pksplit(dz * rs * gq.z + bq.z);
        uint u3 = pksplit(dw * rs * gq.w + bq.w);
        size_t o = (size_t)(m0 + r) * DM + lane * 4;
        *reinterpret_cast<ushort4*>(g_hh + o) =
            make_ushort4((ushort)u0, (ushort)u1, (ushort)u2, (ushort)u3);
        *reinterpret_cast<ushort4*>(g_hl + o) =
            make_ushort4((ushort)(u0 >> 16), (ushort)(u1 >> 16),
                         (ushort)(u2 >> 16), (ushort)(u3 >> 16));
    }
}

// ---------------------------------------------------------------------------
// K4: fused FFN  h = h + relu(h @ W1 + b1) @ W2 + b2  (pipelined cp.async)
// ---------------------------------------------------------------------------
__global__ __launch_bounds__(256) void ffn_fused(const ushort* __restrict__ W1h,
                                                 const ushort* __restrict__ W1l,
                                                 const ushort* __restrict__ W2h,
                                                 const ushort* __restrict__ W2l,
                                                 const float* __restrict__ b1,
                                                 const float* __restrict__ b2) {
    extern __shared__ char dsm[];
    __shared__ __align__(16) float sB1[DFF], sB2[DM];

    int tid = threadIdx.x, lane = tid & 31, wid = tid >> 5;
    int wm = wid & 3, wn = wid >> 2;
    int gid = lane >> 2, tig = lane & 3;
    uint sb = smem_u32(dsm);
    int m0 = blockIdx.x * 128;

    cpa_tile(g_hh + (size_t)m0 * DM, g_hl + (size_t)m0 * DM, 0, 0, DM, sb + H_HI, tid);
    CP_COMMIT();
    cpa_tile(W1h, W1l, 0, 0, DM, sb + S1_HI, tid);
    CP_COMMIT();

    for (int i = tid; i < DFF; i += 256) sB1[i] = b1[i];
    if (tid < DM) sB2[tid] = b2[tid];
    uint offA[2], offB[4];
    make_offs(lane, wm, wn, offA, offB);
    float acc2[2][8][4];
    zero_acc(acc2);

    for (int c = 0; c < 4; c++) {
        // W2 chunk c prefetch overlaps mma1
        cpa_tile(W2h, W2l, 0, c * 128, DFF, sb + S2_HI, tid);
        CP_COMMIT();
        CP_WAIT(1);                      // H (c==0) and W1c complete
        __syncthreads();

        float acc1[2][8][4];
        zero_acc(acc1);
        mma_chunk(sb + H_HI, sb + H_LO, sb + S1_HI, sb + S1_LO, offA, offB, acc1);
        __syncthreads();                 // S1 (W1c) free

        // relu + bias -> split mid planes into S1
#pragma unroll
        for (int im = 0; im < 2; im++)
#pragma unroll
            for (int in = 0; in < 8; in++)
#pragma unroll
                for (int r = 0; r < 4; r++) {
                    int row = wm * 32 + im * 16 + gid + 8 * (r >> 1);
                    int col = wn * 64 + in * 8 + 2 * tig + (r & 1);
                    float v = fmaxf(acc1[im][in][r] + sB1[c * 128 + col], 0.f);
                    uint u = pksplit(v);
                    *reinterpret_cast<ushort*>(dsm + S1_HI + row * LDT_B + col * 2) =
                        (ushort)(u & 0xffffu);
                    *reinterpret_cast<ushort*>(dsm + S1_LO + row * LDT_B + col * 2) =
                        (ushort)(u >> 16);
                }
        CP_WAIT(0);                      // W2c complete
        __syncthreads();                 // mid visible

        mma_chunk(sb + S1_HI, sb + S1_LO, sb + S2_HI, sb + S2_LO, offA, offB, acc2);
        __syncthreads();                 // S1, S2 free

        if (c < 3) {
            cpa_tile(W1h, W1l, (c + 1) * 128, 0, DM, sb + S1_HI, tid);
            CP_COMMIT();
        }
    }

    float* stage = (float*)(dsm + STAGE_O);
    stage_acc(stage, wm, wn, lane, acc2);
    __syncthreads();

    // epilogue: + b2 + residual (H planes resident in smem), plane stores
#pragma unroll
    for (int i = 0; i < 16; i++) {
        int idx = tid + 256 * i;
        int r = idx >> 5, q = idx & 31;
        float4 v = *reinterpret_cast<const float4*>(&stage[r * 132 + 4 * q]);
        ushort4 hh = *reinterpret_cast<const ushort4*>(dsm + H_HI + r * LDT_B + 8 * q);
        ushort4 hl = *reinterpret_cast<const ushort4*>(dsm + H_LO + r * LDT_B + 8 * q);
        uint u0 = pksplit(v.x + sB2[4 * q]     + bfu(hh.x) + bfu(hl.x));
        uint u1 = pksplit(v.y + sB2[4 * q + 1] + bfu(hh.y) + bfu(hl.y));
        uint u2 = pksplit(v.z + sB2[4 * q + 2] + bfu(hh.z) + bfu(hl.z));
        uint u3 = pksplit(v.w + sB2[4 * q + 3] + bfu(hh.w) + bfu(hl.w));
        size_t o = (size_t)(m0 + r) * DM + 4 * q;
        *reinterpret_cast<ushort4*>(g_hh + o) =
            make_ushort4((ushort)u0, (ushort)u1, (ushort)u2, (ushort)u3);
        *reinterpret_cast<ushort4*>(g_hl + o) =
            make_ushort4((ushort)(u0 >> 16), (ushort)(u1 >> 16),
                         (ushort)(u2 >> 16), (ushort)(u3 >> 16));
    }
}

// ---------------------------------------------------------------------------
// K6: readout
// ---------------------------------------------------------------------------
__global__ __launch_bounds__(128) void readout_kernel(const float4* __restrict__ fcw,
                                                      const float* __restrict__ fcb,
                                                      float* __restrict__ out) {
    int w = threadIdx.x >> 5, lane = threadIdx.x & 31;
    int g = blockIdx.x * 4 + w;
    size_t base = (size_t)g * NPG * DM + 4 * lane;
    float4 s = make_float4(0.f, 0.f, 0.f, 0.f);
#pragma unroll
    for (int j = 0; j < NPG; j++) {
        ushort4 hv = *reinterpret_cast<const ushort4*>(g_hh + base + j * DM);
        ushort4 lv = *reinterpret_cast<const ushort4*>(g_hl + base + j * DM);
        s.x += bfu(hv.x) + bfu(lv.x);
        s.y += bfu(hv.y) + bfu(lv.y);
        s.z += bfu(hv.z) + bfu(lv.z);
        s.w += bfu(hv.w) + bfu(lv.w);
    }
    float4 wv = fcw[lane];
    float p = s.x * wv.x + s.y * wv.y + s.z * wv.z + s.w * wv.w;
#pragma unroll
    for (int o = 16; o; o >>= 1) p += __shfl_xor_sync(0xffffffffu, p, o);
    if (lane == 0)
        out[g] = 1.f / (1.f + expf(-(p * (1.f / 9.f) + fcb[0])));
}

// ---------------------------------------------------------------------------
// Launcher
// ---------------------------------------------------------------------------
extern "C" void kernel_launch(void* const* d_in, const int* in_sizes, int n_in,
                              void* d_out, int out_size) {
    const float* op_table   = (const float*)d_in[0];
    const float* device_emb = (const float*)d_in[1];
    const float* Wg         = (const float*)d_in[2];
    const float* bg         = (const float*)d_in[3];
    const float* ln_g       = (const float*)d_in[4];
    const float* ln_b       = (const float*)d_in[5];
    const float* W1         = (const float*)d_in[6];
    const float* b1         = (const float*)d_in[7];
    const float* W2         = (const float*)d_in[8];
    const float* b2         = (const float*)d_in[9];
    const float* fc_w       = (const float*)d_in[10];
    const float* fc_b       = (const float*)d_in[11];
    const int*   op_idx     = (const int*)d_in[12];
    const int*   src        = (const int*)d_in[13];
    const int*   dst        = (const int*)d_in[14];
    float* out = (float*)d_out;

    cudaFuncSetAttribute(gcn_mma,   cudaFuncAttributeMaxDynamicSharedMemorySize, GM_SMEM);
    cudaFuncSetAttribute(ffn_fused, cudaFuncAttributeMaxDynamicSharedMemorySize, FF_SMEM);

    ushort *wgh, *wgl, *w1h, *w1l, *w2h, *w2l;
    cudaGetSymbolAddress((void**)&wgh, g_Wgh);
    cudaGetSymbolAddress((void**)&wgl, g_Wgl);
    cudaGetSymbolAddress((void**)&w1h, g_W1h);
    cudaGetSymbolAddress((void**)&w1l, g_W1l);
    cudaGetSymbolAddress((void**)&w2h, g_W2h);
    cudaGetSymbolAddress((void**)&w2l, g_W2l);

    prep_w<<<dim3((DM * DM + 255) / 256, 1, NL), 256>>>(Wg, wgh, wgl, DM, DM);
    prep_w<<<dim3((DM * DFF + 255) / 256, 1, NL), 256>>>(W1, w1h, w1l, DM, DFF);
    prep_w<<<dim3((DM * DFF + 255) / 256, 1, NL), 256>>>(W2, w2h, w2l, DFF, DM);

    deg_kernel<<<BGR / 256, 256>>>(dst);
    embed_kernel<<<(NNODE * 32) / 256, 256>>>(
        (const float4*)op_table, (const float4*)device_emb, op_idx);

    for (int l = 0; l < NL; l++) {
        size_t o1 = (size_t)l * DM * DM, o2 = (size_t)l * DFF * DM, o3 = (size_t)l * DM * DFF;
        agg_kernel<<<BGR, 128>>>(src, dst);
        gcn_mma<<<NTILES, 256, GM_SMEM>>>(
            wgh + o1, wgl + o1, bg + l * DM, ln_g + l * DM, ln_b + l * DM);
        ffn_fused<<<NTILES, 256, FF_SMEM>>>(
            w1h + o2, w1l + o2, w2h + o3, w2l + o3, b1 + l * DFF, b2 + l * DM);
    }

    readout_kernel<<<BGR / 4, 128>>>((const float4*)fc_w, fc_b, out);
}

// round 10
// speedup vs baseline: 1.2770x; 1.0450x over previous
#include <cuda_runtime.h>
#include <cuda_bf16.h>
#include <cstdint>
#include <math.h>

typedef unsigned int uint;
typedef unsigned long long ull;
typedef unsigned short ushort;

// ---------------------------------------------------------------------------
// Problem constants
// ---------------------------------------------------------------------------
#define BGR   16384
#define NPG   9
#define NNODE (BGR * NPG)      // 147456
#define DM    128
#define DFF   512
#define NL    4
#define EPG   16

#define NTILES (NNODE / 128)   // 1152

// smem tile geometry: 128 rows x 128 bf16, padded row stride 272 B (17x16B)
#define LDT_B   272
#define TILE_B  (128 * LDT_B)          // 34816

// fused layer-GEMM kernel: P pair (agg->H), Q pair (Wg->stage->W2c), R pair (W1c->mid)
#define P_HI    0
#define P_LO    TILE_B
#define Q_HI    (2 * TILE_B)
#define Q_LO    (3 * TILE_B)
#define R_HI    (4 * TILE_B)
#define R_LO    (5 * TILE_B)
#define LM_SMEM (6 * TILE_B)           // 208896

// ---------------------------------------------------------------------------
// Scratch (device globals) — activations and weights as separate hi/lo
// bf16 planes; value = hi + lo.
// ---------------------------------------------------------------------------
__device__ ushort g_hh [(size_t)NNODE * DM], g_hl [(size_t)NNODE * DM];
__device__ ushort g_agh[(size_t)NNODE * DM], g_agl[(size_t)NNODE * DM];
__device__ float  g_inv[NNODE];
__device__ ushort g_Wgh[(size_t)NL * DM * DM],  g_Wgl[(size_t)NL * DM * DM];
__device__ ushort g_W1h[(size_t)NL * DFF * DM], g_W1l[(size_t)NL * DFF * DM];
__device__ ushort g_W2h[(size_t)NL * DM * DFF], g_W2l[(size_t)NL * DM * DFF];

// ---------------------------------------------------------------------------
// helpers
// ---------------------------------------------------------------------------
__device__ __forceinline__ uint smem_u32(const void* p) {
    uint a;
    asm("{ .reg .u64 t; cvta.to.shared.u64 t, %1; cvt.u32.u64 %0, t; }" : "=r"(a) : "l"(p));
    return a;
}
__device__ __forceinline__ void ldsm4(uint* r, uint addr) {
    asm volatile("ldmatrix.sync.aligned.m8n8.x4.shared.b16 {%0,%1,%2,%3}, [%4];"
        : "=r"(r[0]), "=r"(r[1]), "=r"(r[2]), "=r"(r[3]) : "r"(addr));
}
__device__ __forceinline__ void mma_bf16(float* c, const uint* a, const uint* b) {
    asm volatile("mma.sync.aligned.m16n8k16.row.col.f32.bf16.bf16.f32 "
        "{%0,%1,%2,%3}, {%4,%5,%6,%7}, {%8,%9}, {%0,%1,%2,%3};"
        : "+f"(c[0]), "+f"(c[1]), "+f"(c[2]), "+f"(c[3])
        : "r"(a[0]), "r"(a[1]), "r"(a[2]), "r"(a[3]), "r"(b[0]), "r"(b[1]));
}
__device__ __forceinline__ uint pksplit(float v) {
    __nv_bfloat16 h = __float2bfloat16(v);
    __nv_bfloat16 l = __float2bfloat16(v - __bfloat162float(h));
    return (uint)__bfloat16_as_ushort(h) | ((uint)__bfloat16_as_ushort(l) << 16);
}
__device__ __forceinline__ float bfu(uint s) {
    return __bfloat162float(__ushort_as_bfloat16((ushort)s));
}
// split two adjacent values into packed hi-pair / lo-pair (elem0 in low 16)
__device__ __forceinline__ void pk2split(float v0, float v1, uint &hi2, uint &lo2) {
    asm("cvt.rn.bf16x2.f32 %0, %1, %2;" : "=r"(hi2) : "f"(v1), "f"(v0));
    float h0 = __uint_as_float(hi2 << 16);
    float h1 = __uint_as_float(hi2 & 0xffff0000u);
    float l0 = v0 - h0, l1 = v1 - h1;
    asm("cvt.rn.bf16x2.f32 %0, %1, %2;" : "=r"(lo2) : "f"(l1), "f"(l0));
}

#define CP16(sm, gp) do {                                                     \
    unsigned long long _g;                                                    \
    asm("cvta.to.global.u64 %0, %1;" : "=l"(_g) : "l"(gp));                   \
    asm volatile("cp.async.cg.shared.global [%0], [%1], 16;" :: "r"(sm), "l"(_g)); \
} while (0)
#define CP_COMMIT() asm volatile("cp.async.commit_group;" ::: "memory")
#define CP_WAIT(n)  asm volatile("cp.async.wait_group %0;" :: "n"(n) : "memory")

// async load of a 128x128 bf16 plane pair into (sbase, sbase+TILE_B)
__device__ __forceinline__ void cpa_tile(const ushort* __restrict__ gh,
                                         const ushort* __restrict__ gl,
                                         int row0, int col0, int ldg,
                                         uint sbase, int tid) {
#pragma unroll
    for (int i = 0; i < 8; i++) {
        int idx = tid + 256 * i;       // 2048 granules per plane
        int r = idx >> 4, g = idx & 15;
        uint d = sbase + r * LDT_B + g * 16;
        CP16(d,          gh + (size_t)(row0 + r) * ldg + col0 + g * 8);
        CP16(d + TILE_B, gl + (size_t)(row0 + r) * ldg + col0 + g * 8);
    }
}

// ---------------------------------------------------------------------------
// MMA core: warp tile 32(M) x 64(N), K=128 chunk, 3-pass split accumulate
// ---------------------------------------------------------------------------
__device__ __forceinline__ void mma_chunk(uint aHi, uint aLo, uint bHi, uint bLo,
                                          const uint* offA, const uint* offB,
                                          float acc[2][8][4]) {
#pragma unroll
    for (int ks = 0; ks < 8; ks++) {
        uint kb = ks * 32;
        uint ah[2][4], al[2][4], bh[4][4], bl[4][4];
        ldsm4(ah[0], aHi + offA[0] + kb);
        ldsm4(ah[1], aHi + offA[1] + kb);
        ldsm4(al[0], aLo + offA[0] + kb);
        ldsm4(al[1], aLo + offA[1] + kb);
#pragma unroll
        for (int p = 0; p < 4; p++) {
            ldsm4(bh[p], bHi + offB[p] + kb);
            ldsm4(bl[p], bLo + offB[p] + kb);
        }
#pragma unroll
        for (int im = 0; im < 2; im++)
#pragma unroll
            for (int p = 0; p < 4; p++) {
                mma_bf16(acc[im][2 * p],     ah[im], &bh[p][0]);
                mma_bf16(acc[im][2 * p + 1], ah[im], &bh[p][2]);
                mma_bf16(acc[im][2 * p],     ah[im], &bl[p][0]);
                mma_bf16(acc[im][2 * p + 1], ah[im], &bl[p][2]);
                mma_bf16(acc[im][2 * p],     al[im], &bh[p][0]);
                mma_bf16(acc[im][2 * p + 1], al[im], &bh[p][2]);
            }
    }
}

__device__ __forceinline__ void zero_acc(float acc[2][8][4]) {
#pragma unroll
    for (int im = 0; im < 2; im++)
#pragma unroll
        for (int in = 0; in < 8; in++)
#pragma unroll
            for (int r = 0; r < 4; r++) acc[im][in][r] = 0.f;
}

__device__ __forceinline__ void make_offs(int lane, int wm, int wn,
                                          uint* offA, uint* offB) {
#pragma unroll
    for (int im = 0; im < 2; im++)
        offA[im] = (uint)((wm * 32 + im * 16 + (lane & 15)) * LDT_B + ((lane >> 4) << 4));
#pragma unroll
    for (int p = 0; p < 4; p++)
        offB[p] = (uint)((wn * 64 + p * 16 + (lane & 7) + ((lane >> 4) << 3)) * LDT_B
                         + (((lane >> 3) & 1) << 4));
}

// stage acc (raw) into f32 smem [128][132]
__device__ __forceinline__ void stage_acc(float* st, int wm, int wn, int lane,
                                          float acc[2][8][4]) {
    int gid = lane >> 2, tig = lane & 3;
#pragma unroll
    for (int im = 0; im < 2; im++)
#pragma unroll
        for (int in = 0; in < 8; in++)
#pragma unroll
            for (int r = 0; r < 4; r++) {
                int row = wm * 32 + im * 16 + gid + 8 * (r >> 1);
                int col = wn * 64 + in * 8 + 2 * tig + (r & 1);
                st[row * 132 + col] = acc[im][in][r];
            }
}

// ---------------------------------------------------------------------------
// K0: degree -> inv_sqrt_deg
// ---------------------------------------------------------------------------
__global__ void deg_kernel(const int* __restrict__ dst) {
    int g = blockIdx.x * blockDim.x + threadIdx.x;
    if (g >= BGR) return;
    int base = g * NPG;
    int cnt[NPG];
#pragma unroll
    for (int j = 0; j < NPG; j++) cnt[j] = 1;
#pragma unroll
    for (int e = 0; e < EPG; e++) {
        int dl = dst[g * EPG + e] - base;
#pragma unroll
        for (int j = 0; j < NPG; j++) cnt[j] += (dl == j) ? 1 : 0;
    }
#pragma unroll
    for (int j = 0; j < NPG; j++)
        g_inv[base + j] = rsqrtf((float)cnt[j]);
}

// ---------------------------------------------------------------------------
// K1: embedding -> h planes
// ---------------------------------------------------------------------------
__global__ void embed_kernel(const float4* __restrict__ opt,
                             const float4* __restrict__ de,
                             const int* __restrict__ op_idx) {
    int idx = blockIdx.x * blockDim.x + threadIdx.x;   // NNODE*32
    int n = idx >> 5, c = idx & 31;
    float4 t = opt[op_idx[n] * 32 + c];
    float4 d = de[c];
    uint h0, l0, h1, l1;
    pk2split(t.x + d.x, t.y + d.y, h0, l0);
    pk2split(t.z + d.z, t.w + d.w, h1, l1);
    size_t o = (size_t)n * DM + 4 * c;
    *reinterpret_cast<uint2*>(g_hh + o) = make_uint2(h0, h1);
    *reinterpret_cast<uint2*>(g_hl + o) = make_uint2(l0, l1);
}

// ---------------------------------------------------------------------------
// K2: per-graph aggregation (planes in / planes out, no atomics)
// ---------------------------------------------------------------------------
__global__ __launch_bounds__(128) void agg_kernel(const int* __restrict__ src,
                                                  const int* __restrict__ dst) {
    __shared__ float hs[NPG * DM];
    __shared__ float ag[NPG * DM];
    __shared__ float invs[NPG];
    __shared__ float we[EPG];
    __shared__ int sl[EPG], dl[EPG];

    int g = blockIdx.x, t = threadIdx.x;
    int nbase = g * NPG;
    if (t < NPG) invs[t] = g_inv[nbase + t];
    if (t < EPG) {
        sl[t] = src[g * EPG + t] - nbase;
        dl[t] = dst[g * EPG + t] - nbase;
    }
    __syncthreads();
    if (t < EPG) we[t] = invs[sl[t]] * invs[dl[t]];
#pragma unroll
    for (int j = 0; j < NPG; j++) {
        size_t o = (size_t)(nbase + j) * DM + t;
        float v = bfu(g_hh[o]) + bfu(g_hl[o]);
        hs[j * DM + t] = v;
        ag[j * DM + t] = invs[j] * invs[j] * v;
    }
    __syncthreads();
#pragma unroll
    for (int e = 0; e < EPG; e++)
        ag[dl[e] * DM + t] += we[e] * hs[sl[e] * DM + t];
#pragma unroll
    for (int j = 0; j < NPG; j++) {
        uint u = pksplit(ag[j * DM + t]);
        size_t o = (size_t)(nbase + j) * DM + t;
        g_agh[o] = (ushort)(u & 0xffffu);
        g_agl[o] = (ushort)(u >> 16);
    }
}

// ---------------------------------------------------------------------------
// Weight prep: planes[c][r] = split(src[r][c])
// ---------------------------------------------------------------------------
__global__ void prep_w(const float* __restrict__ src,
                       ushort* __restrict__ dh, ushort* __restrict__ dl,
                       int R, int C) {
    int l = blockIdx.z;
    src += (size_t)l * R * C;
    dh  += (size_t)l * R * C;
    dl  += (size_t)l * R * C;
    int n = blockIdx.x * blockDim.x + threadIdx.x;
    if (n >= R * C) return;
    int c = n / R, r = n % R;
    uint u = pksplit(src[(size_t)r * C + c]);
    dh[n] = (ushort)(u & 0xffffu);
    dl[n] = (ushort)(u >> 16);
}

// ---------------------------------------------------------------------------
// K3: fused layer GEMMs: h = hLN + relu(hLN @ W1 + b1) @ W2 + b2,
//     hLN = LN(relu(agg @ Wg + bg))   — hLN never leaves smem.
// ---------------------------------------------------------------------------
__global__ __launch_bounds__(256) void layer_mm(
    const ushort* __restrict__ Wgh, const ushort* __restrict__ Wgl,
    const ushort* __restrict__ W1h, const ushort* __restrict__ W1l,
    const ushort* __restrict__ W2h, const ushort* __restrict__ W2l,
    const float* __restrict__ bg, const float* __restrict__ lng,
    const float* __restrict__ lnb, const float* __restrict__ b1,
    const float* __restrict__ b2) {

    extern __shared__ char dsm[];
    __shared__ __align__(16) float sBg[DM], sLng[DM], sLnb[DM], sB1[DFF], sB2[DM];

    int tid = threadIdx.x, lane = tid & 31, wid = tid >> 5;
    int wm = wid & 3, wn = wid >> 2;
    int gid = lane >> 2, tig = lane & 3;
    uint sb = smem_u32(dsm);
    int m0 = blockIdx.x * 128;

    // async: agg -> P, Wg -> Q (group 1); W1c0 -> R (group 2)
    cpa_tile(g_agh + (size_t)m0 * DM, g_agl + (size_t)m0 * DM, 0, 0, DM, sb + P_HI, tid);
    cpa_tile(Wgh, Wgl, 0, 0, DM, sb + Q_HI, tid);
    CP_COMMIT();
    cpa_tile(W1h, W1l, 0, 0, DM, sb + R_HI, tid);
    CP_COMMIT();

    if (tid < DM) { sBg[tid] = bg[tid]; sLng[tid] = lng[tid]; sLnb[tid] = lnb[tid]; sB2[tid] = b2[tid]; }
    for (int i = tid; i < DFF; i += 256) sB1[i] = b1[i];
    uint offA[2], offB[4];
    make_offs(lane, wm, wn, offA, offB);

    // GCN mma: acc = agg @ Wg
    float acc[2][8][4];
    zero_acc(acc);
    CP_WAIT(1);
    __syncthreads();
    mma_chunk(sb + P_HI, sb + P_LO, sb + Q_HI, sb + Q_LO, offA, offB, acc);
    __syncthreads();                               // P (agg), Q (Wg) dead

    float* stage = (float*)(dsm + Q_HI);
    stage_acc(stage, wm, wn, lane, acc);
    __syncthreads();

    // LN -> H planes in P
    {
        float4 gq = *reinterpret_cast<const float4*>(&sLng[lane * 4]);
        float4 bq = *reinterpret_cast<const float4*>(&sLnb[lane * 4]);
        float4 bb = *reinterpret_cast<const float4*>(&sBg[lane * 4]);
        for (int it = 0; it < 16; it++) {
            int r = wid * 16 + it;
            float4 x = *reinterpret_cast<const float4*>(&stage[r * 132 + lane * 4]);
            x.x = fmaxf(x.x + bb.x, 0.f); x.y = fmaxf(x.y + bb.y, 0.f);
            x.z = fmaxf(x.z + bb.z, 0.f); x.w = fmaxf(x.w + bb.w, 0.f);
            float s = x.x + x.y + x.z + x.w;
#pragma unroll
            for (int o = 16; o; o >>= 1) s += __shfl_xor_sync(0xffffffffu, s, o);
            float mu = s * (1.f / 128.f);
            float dx = x.x - mu, dy = x.y - mu, dz = x.z - mu, dw = x.w - mu;
            float q = dx * dx + dy * dy + dz * dz + dw * dw;
#pragma unroll
            for (int o = 16; o; o >>= 1) q += __shfl_xor_sync(0xffffffffu, q, o);
            float rs = rsqrtf(q * (1.f / 128.f) + 1e-5f);
            uint h0, l0, h1, l1;
            pk2split(dx * rs * gq.x + bq.x, dy * rs * gq.y + bq.y, h0, l0);
            pk2split(dz * rs * gq.z + bq.z, dw * rs * gq.w + bq.w, h1, l1);
            *reinterpret_cast<uint2*>(dsm + P_HI + r * LDT_B + lane * 8) = make_uint2(h0, h1);
            *reinterpret_cast<uint2*>(dsm + P_LO + r * LDT_B + lane * 8) = make_uint2(l0, l1);
        }
    }
    __syncthreads();                               // H ready; stage (Q) dead

    // FFN loop: per chunk c — W2c -> Q (async over mma1), mid -> R
    float acc2[2][8][4];
    zero_acc(acc2);
    for (int c = 0; c < 4; c++) {
        cpa_tile(W2h, W2l, 0, c * 128, DFF, sb + Q_HI, tid);
        CP_COMMIT();
        CP_WAIT(1);                                // W1c resident in R
        __syncthreads();

        float acc1[2][8][4];
        zero_acc(acc1);
        mma_chunk(sb + P_HI, sb + P_LO, sb + R_HI, sb + R_LO, offA, offB, acc1);
        __syncthreads();                           // R (W1c) dead

        // relu + bias -> packed mid planes into R (u32 stores, conflict-free)
#pragma unroll
        for (int im = 0; im < 2; im++)
#pragma unroll
            for (int in = 0; in < 8; in++)
#pragma unroll
                for (int pr = 0; pr < 2; pr++) {
                    int row = wm * 32 + im * 16 + gid + 8 * pr;
                    int col = wn * 64 + in * 8 + 2 * tig;
                    float v0 = fmaxf(acc1[im][in][2 * pr]     + sB1[c * 128 + col], 0.f);
                    float v1 = fmaxf(acc1[im][in][2 * pr + 1] + sB1[c * 128 + col + 1], 0.f);
                    uint h2, l2;
                    pk2split(v0, v1, h2, l2);
                    *reinterpret_cast<uint*>(dsm + R_HI + row * LDT_B + col * 2) = h2;
                    *reinterpret_cast<uint*>(dsm + R_LO + row * LDT_B + col * 2) = l2;
                }
        CP_WAIT(0);                                // W2c resident in Q
        __syncthreads();                           // mid visible

        mma_chunk(sb + R_HI, sb + R_LO, sb + Q_HI, sb + Q_LO, offA, offB, acc2);
        __syncthreads();                           // Q, R dead

        if (c < 3) {
            cpa_tile(W1h, W1l, (c + 1) * 128, 0, DM, sb + R_HI, tid);
            CP_COMMIT();
        }
    }

    stage_acc(stage, wm, wn, lane, acc2);          // stage back into Q region
    __syncthreads();

    // epilogue: h_out = hLN (P planes) + ffn + b2 -> global planes
#pragma unroll
    for (int i = 0; i < 16; i++) {
        int idx = tid + 256 * i;
        int r = idx >> 5, q = idx & 31;
        float4 v = *reinterpret_cast<const float4*>(&stage[r * 132 + 4 * q]);
        ushort4 hh = *reinterpret_cast<const ushort4*>(dsm + P_HI + r * LDT_B + 8 * q);
        ushort4 hl = *reinterpret_cast<const ushort4*>(dsm + P_LO + r * LDT_B + 8 * q);
        float o0 = v.x + sB2[4 * q]     + bfu(hh.x) + bfu(hl.x);
        float o1 = v.y + sB2[4 * q + 1] + bfu(hh.y) + bfu(hl.y);
        float o2 = v.z + sB2[4 * q + 2] + bfu(hh.z) + bfu(hl.z);
        float o3 = v.w + sB2[4 * q + 3] + bfu(hh.w) + bfu(hl.w);
        uint h0, l0, h1, l1;
        pk2split(o0, o1, h0, l0);
        pk2split(o2, o3, h1, l1);
        size_t o = (size_t)(m0 + r) * DM + 4 * q;
        *reinterpret_cast<uint2*>(g_hh + o) = make_uint2(h0, h1);
        *reinterpret_cast<uint2*>(g_hl + o) = make_uint2(l0, l1);
    }
}

// ---------------------------------------------------------------------------
// K6: readout
// ---------------------------------------------------------------------------
__global__ __launch_bounds__(128) void readout_kernel(const float4* __restrict__ fcw,
                                                      const float* __restrict__ fcb,
                                                      float* __restrict__ out) {
    int w = threadIdx.x >> 5, lane = threadIdx.x & 31;
    int g = blockIdx.x * 4 + w;
    size_t base = (size_t)g * NPG * DM + 4 * lane;
    float4 s = make_float4(0.f, 0.f, 0.f, 0.f);
#pragma unroll
    for (int j = 0; j < NPG; j++) {
        ushort4 hv = *reinterpret_cast<const ushort4*>(g_hh + base + j * DM);
        ushort4 lv = *reinterpret_cast<const ushort4*>(g_hl + base + j * DM);
        s.x += bfu(hv.x) + bfu(lv.x);
        s.y += bfu(hv.y) + bfu(lv.y);
        s.z += bfu(hv.z) + bfu(lv.z);
        s.w += bfu(hv.w) + bfu(lv.w);
    }
    float4 wv = fcw[lane];
    float p = s.x * wv.x + s.y * wv.y + s.z * wv.z + s.w * wv.w;
#pragma unroll
    for (int o = 16; o; o >>= 1) p += __shfl_xor_sync(0xffffffffu, p, o);
    if (lane == 0)
        out[g] = 1.f / (1.f + expf(-(p * (1.f / 9.f) + fcb[0])));
}

// ---------------------------------------------------------------------------
// Launcher
// ---------------------------------------------------------------------------
extern "C" void kernel_launch(void* const* d_in, const int* in_sizes, int n_in,
                              void* d_out, int out_size) {
    const float* op_table   = (const float*)d_in[0];
    const float* device_emb = (const float*)d_in[1];
    const float* Wg         = (const float*)d_in[2];
    const float* bg         = (const float*)d_in[3];
    const float* ln_g       = (const float*)d_in[4];
    const float* ln_b       = (const float*)d_in[5];
    const float* W1         = (const float*)d_in[6];
    const float* b1         = (const float*)d_in[7];
    const float* W2         = (const float*)d_in[8];
    const float* b2         = (const float*)d_in[9];
    const float* fc_w       = (const float*)d_in[10];
    const float* fc_b       = (const float*)d_in[11];
    const int*   op_idx     = (const int*)d_in[12];
    const int*   src        = (const int*)d_in[13];
    const int*   dst        = (const int*)d_in[14];
    float* out = (float*)d_out;

    cudaFuncSetAttribute(layer_mm, cudaFuncAttributeMaxDynamicSharedMemorySize, LM_SMEM);

    ushort *wgh, *wgl, *w1h, *w1l, *w2h, *w2l;
    cudaGetSymbolAddress((void**)&wgh, g_Wgh);
    cudaGetSymbolAddress((void**)&wgl, g_Wgl);
    cudaGetSymbolAddress((void**)&w1h, g_W1h);
    cudaGetSymbolAddress((void**)&w1l, g_W1l);
    cudaGetSymbolAddress((void**)&w2h, g_W2h);
    cudaGetSymbolAddress((void**)&w2l, g_W2l);

    prep_w<<<dim3((DM * DM + 255) / 256, 1, NL), 256>>>(Wg, wgh, wgl, DM, DM);
    prep_w<<<dim3((DM * DFF + 255) / 256, 1, NL), 256>>>(W1, w1h, w1l, DM, DFF);
    prep_w<<<dim3((DM * DFF + 255) / 256, 1, NL), 256>>>(W2, w2h, w2l, DFF, DM);

    deg_kernel<<<BGR / 256, 256>>>(dst);
    embed_kernel<<<(NNODE * 32) / 256, 256>>>(
        (const float4*)op_table, (const float4*)device_emb, op_idx);

    for (int l = 0; l < NL; l++) {
        size_t o1 = (size_t)l * DM * DM, o2 = (size_t)l * DFF * DM, o3 = (size_t)l * DM * DFF;
        agg_kernel<<<BGR, 128>>>(src, dst);
        layer_mm<<<NTILES, 256, LM_SMEM>>>(
            wgh + o1, wgl + o1, w1h + o2, w1l + o2, w2h + o3, w2l + o3,
            bg + l * DM, ln_g + l * DM, ln_b + l * DM, b1 + l * DFF, b2 + l * DM);
    }

    readout_kernel<<<BGR / 4, 128>>>((const float4*)fc_w, fc_b, out);
}

// round 12
// speedup vs baseline: 1.3094x; 1.0254x over previous
#include <cuda_runtime.h>
#include <cuda_bf16.h>
#include <cstdint>
#include <math.h>

typedef unsigned int uint;
typedef unsigned long long ull;
typedef unsigned short ushort;

// ---------------------------------------------------------------------------
// Problem constants
// ---------------------------------------------------------------------------
#define BGR   16384
#define NPG   9
#define NNODE (BGR * NPG)      // 147456
#define DM    128
#define DFF   512
#define NL    4
#define EPG   16

#define NTILES (NNODE / 128)   // 1152

// smem tile geometry: 128 rows x 128 bf16, padded row stride 272 B (17x16B)
#define LDT_B   272
#define TILE_B  (128 * LDT_B)          // 34816

// layer kernel smem: P pair (agg), Q pair (Wg -> W2c), R pair (W1c)
#define P_HI    0
#define P_LO    TILE_B
#define Q_HI    (2 * TILE_B)
#define Q_LO    (3 * TILE_B)
#define R_HI    (4 * TILE_B)
#define R_LO    (5 * TILE_B)
#define LM_SMEM (6 * TILE_B)           // 208896

// ---------------------------------------------------------------------------
// Scratch (device globals) — activations and weights as separate hi/lo
// bf16 planes; value = hi + lo.
// ---------------------------------------------------------------------------
__device__ ushort g_hh [(size_t)NNODE * DM], g_hl [(size_t)NNODE * DM];
__device__ ushort g_agh[(size_t)NNODE * DM], g_agl[(size_t)NNODE * DM];
__device__ float  g_inv[NNODE];
__device__ ushort g_Wgh[(size_t)NL * DM * DM],  g_Wgl[(size_t)NL * DM * DM];
__device__ ushort g_W1h[(size_t)NL * DFF * DM], g_W1l[(size_t)NL * DFF * DM];
__device__ ushort g_W2h[(size_t)NL * DM * DFF], g_W2l[(size_t)NL * DM * DFF];

// ---------------------------------------------------------------------------
// helpers
// ---------------------------------------------------------------------------
__device__ __forceinline__ uint smem_u32(const void* p) {
    uint a;
    asm("{ .reg .u64 t; cvta.to.shared.u64 t, %1; cvt.u32.u64 %0, t; }" : "=r"(a) : "l"(p));
    return a;
}
__device__ __forceinline__ void ldsm4(uint* r, uint addr) {
    asm volatile("ldmatrix.sync.aligned.m8n8.x4.shared.b16 {%0,%1,%2,%3}, [%4];"
        : "=r"(r[0]), "=r"(r[1]), "=r"(r[2]), "=r"(r[3]) : "r"(addr));
}
__device__ __forceinline__ void mma_bf16(float* c, const uint* a, const uint* b) {
    asm volatile("mma.sync.aligned.m16n8k16.row.col.f32.bf16.bf16.f32 "
        "{%0,%1,%2,%3}, {%4,%5,%6,%7}, {%8,%9}, {%0,%1,%2,%3};"
        : "+f"(c[0]), "+f"(c[1]), "+f"(c[2]), "+f"(c[3])
        : "r"(a[0]), "r"(a[1]), "r"(a[2]), "r"(a[3]), "r"(b[0]), "r"(b[1]));
}
__device__ __forceinline__ uint pksplit(float v) {
    __nv_bfloat16 h = __float2bfloat16(v);
    __nv_bfloat16 l = __float2bfloat16(v - __bfloat162float(h));
    return (uint)__bfloat16_as_ushort(h) | ((uint)__bfloat16_as_ushort(l) << 16);
}
__device__ __forceinline__ float bfu(uint s) {
    return __bfloat162float(__ushort_as_bfloat16((ushort)s));
}
// split two adjacent values into packed hi-pair / lo-pair (elem0 in low 16)
__device__ __forceinline__ void pk2split(float v0, float v1, uint &hi2, uint &lo2) {
    asm("cvt.rn.bf16x2.f32 %0, %1, %2;" : "=r"(hi2) : "f"(v1), "f"(v0));
    float h0 = __uint_as_float(hi2 << 16);
    float h1 = __uint_as_float(hi2 & 0xffff0000u);
    float l0 = v0 - h0, l1 = v1 - h1;
    asm("cvt.rn.bf16x2.f32 %0, %1, %2;" : "=r"(lo2) : "f"(l1), "f"(l0));
}

#define CP16(sm, gp) do {                                                     \
    unsigned long long _g;                                                    \
    asm("cvta.to.global.u64 %0, %1;" : "=l"(_g) : "l"(gp));                   \
    asm volatile("cp.async.cg.shared.global [%0], [%1], 16;" :: "r"(sm), "l"(_g)); \
} while (0)
#define CP_COMMIT() asm volatile("cp.async.commit_group;" ::: "memory")
#define CP_WAIT(n)  asm volatile("cp.async.wait_group %0;" :: "n"(n) : "memory")

// async load of a 128x128 bf16 plane pair into (sbase, sbase+TILE_B)
__device__ __forceinline__ void cpa_tile(const ushort* __restrict__ gh,
                                         const ushort* __restrict__ gl,
                                         int row0, int col0, int ldg,
                                         uint sbase, int tid) {
#pragma unroll
    for (int i = 0; i < 8; i++) {
        int idx = tid + 256 * i;       // 2048 granules per plane
        int r = idx >> 4, g = idx & 15;
        uint d = sbase + r * LDT_B + g * 16;
        CP16(d,          gh + (size_t)(row0 + r) * ldg + col0 + g * 8);
        CP16(d + TILE_B, gl + (size_t)(row0 + r) * ldg + col0 + g * 8);
    }
}

// ---------------------------------------------------------------------------
// full-N MMA: warp tile 16(M) x 128(N), A fragments in REGISTERS,
// B tile pair in smem. 3-pass split accumulate (AhBh + AhBl + AlBh).
// ---------------------------------------------------------------------------
__device__ __forceinline__ void mma_fullN(const uint aH[8][4], const uint aL[8][4],
                                          uint bHi, uint bLo, uint offB,
                                          float acc[16][4]) {
#pragma unroll
    for (int ks = 0; ks < 8; ks++) {
        uint kb = ks * 32;
#pragma unroll
        for (int pp = 0; pp < 4; pp++) {
            uint ob0 = offB + (2 * pp) * 16 * LDT_B + kb;
            uint ob1 = ob0 + 16 * LDT_B;
            uint bh0[4], bl0[4], bh1[4], bl1[4];
            ldsm4(bh0, bHi + ob0); ldsm4(bl0, bLo + ob0);
            ldsm4(bh1, bHi + ob1); ldsm4(bl1, bLo + ob1);
            mma_bf16(acc[4 * pp + 0], aH[ks], &bh0[0]);
            mma_bf16(acc[4 * pp + 1], aH[ks], &bh0[2]);
            mma_bf16(acc[4 * pp + 2], aH[ks], &bh1[0]);
            mma_bf16(acc[4 * pp + 3], aH[ks], &bh1[2]);
            mma_bf16(acc[4 * pp + 0], aH[ks], &bl0[0]);
            mma_bf16(acc[4 * pp + 1], aH[ks], &bl0[2]);
            mma_bf16(acc[4 * pp + 2], aH[ks], &bl1[0]);
            mma_bf16(acc[4 * pp + 3], aH[ks], &bl1[2]);
            mma_bf16(acc[4 * pp + 0], aL[ks], &bh0[0]);
            mma_bf16(acc[4 * pp + 1], aL[ks], &bh0[2]);
            mma_bf16(acc[4 * pp + 2], aL[ks], &bh1[0]);
            mma_bf16(acc[4 * pp + 3], aL[ks], &bh1[2]);
        }
    }
}

// ---------------------------------------------------------------------------
// K0: degree -> inv_sqrt_deg
// ---------------------------------------------------------------------------
__global__ void deg_kernel(const int* __restrict__ dst) {
    int g = blockIdx.x * blockDim.x + threadIdx.x;
    if (g >= BGR) return;
    int base = g * NPG;
    int cnt[NPG];
#pragma unroll
    for (int j = 0; j < NPG; j++) cnt[j] = 1;
#pragma unroll
    for (int e = 0; e < EPG; e++) {
        int dl = dst[g * EPG + e] - base;
#pragma unroll
        for (int j = 0; j < NPG; j++) cnt[j] += (dl == j) ? 1 : 0;
    }
#pragma unroll
    for (int j = 0; j < NPG; j++)
        g_inv[base + j] = rsqrtf((float)cnt[j]);
}

// ---------------------------------------------------------------------------
// K1: embedding -> h planes
// ---------------------------------------------------------------------------
__global__ void embed_kernel(const float4* __restrict__ opt,
                             const float4* __restrict__ de,
                             const int* __restrict__ op_idx) {
    int idx = blockIdx.x * blockDim.x + threadIdx.x;   // NNODE*32
    int n = idx >> 5, c = idx & 31;
    float4 t = opt[op_idx[n] * 32 + c];
    float4 d = de[c];
    uint h0, l0, h1, l1;
    pk2split(t.x + d.x, t.y + d.y, h0, l0);
    pk2split(t.z + d.z, t.w + d.w, h1, l1);
    size_t o = (size_t)n * DM + 4 * c;
    *reinterpret_cast<uint2*>(g_hh + o) = make_uint2(h0, h1);
    *reinterpret_cast<uint2*>(g_hl + o) = make_uint2(l0, l1);
}

// ---------------------------------------------------------------------------
// K2: per-graph aggregation (planes in / planes out, no atomics)
// ---------------------------------------------------------------------------
__global__ __launch_bounds__(128) void agg_kernel(const int* __restrict__ src,
                                                  const int* __restrict__ dst) {
    __shared__ float hs[NPG * DM];
    __shared__ float ag[NPG * DM];
    __shared__ float invs[NPG];
    __shared__ float we[EPG];
    __shared__ int sl[EPG], dl[EPG];

    int g = blockIdx.x, t = threadIdx.x;
    int nbase = g * NPG;
    if (t < NPG) invs[t] = g_inv[nbase + t];
    if (t < EPG) {
        sl[t] = src[g * EPG + t] - nbase;
        dl[t] = dst[g * EPG + t] - nbase;
    }
    __syncthreads();
    if (t < EPG) we[t] = invs[sl[t]] * invs[dl[t]];
#pragma unroll
    for (int j = 0; j < NPG; j++) {
        size_t o = (size_t)(nbase + j) * DM + t;
        float v = bfu(g_hh[o]) + bfu(g_hl[o]);
        hs[j * DM + t] = v;
        ag[j * DM + t] = invs[j] * invs[j] * v;
    }
    __syncthreads();
#pragma unroll
    for (int e = 0; e < EPG; e++)
        ag[dl[e] * DM + t] += we[e] * hs[sl[e] * DM + t];
#pragma unroll
    for (int j = 0; j < NPG; j++) {
        uint u = pksplit(ag[j * DM + t]);
        size_t o = (size_t)(nbase + j) * DM + t;
        g_agh[o] = (ushort)(u & 0xffffu);
        g_agl[o] = (ushort)(u >> 16);
    }
}

// ---------------------------------------------------------------------------
// Weight prep: planes[c][r] = split(src[r][c])
// ---------------------------------------------------------------------------
__global__ void prep_w(const float* __restrict__ src,
                       ushort* __restrict__ dh, ushort* __restrict__ dl,
                       int R, int C) {
    int l = blockIdx.z;
    src += (size_t)l * R * C;
    dh  += (size_t)l * R * C;
    dl  += (size_t)l * R * C;
    int n = blockIdx.x * blockDim.x + threadIdx.x;
    if (n >= R * C) return;
    int c = n / R, r = n % R;
    uint u = pksplit(src[(size_t)r * C + c]);
    dh[n] = (ushort)(u & 0xffffu);
    dl[n] = (ushort)(u >> 16);
}

// ---------------------------------------------------------------------------
// K3: fused layer GEMMs, register-resident intermediates.
// warp tile 16(M) x 128(N); C-frag of one GEMM feeds A-frag of the next.
// ---------------------------------------------------------------------------
__global__ __launch_bounds__(256) void layer_mm(
    const ushort* __restrict__ Wgh, const ushort* __restrict__ Wgl,
    const ushort* __restrict__ W1h, const ushort* __restrict__ W1l,
    const ushort* __restrict__ W2h, const ushort* __restrict__ W2l,
    const float* __restrict__ bg, const float* __restrict__ lng,
    const float* __restrict__ lnb, const float* __restrict__ b1,
    const float* __restrict__ b2) {

    extern __shared__ char dsm[];
    __shared__ __align__(16) float sBg[DM], sLng[DM], sLnb[DM], sB1[DFF], sB2[DM];

    int tid = threadIdx.x, lane = tid & 31, wid = tid >> 5;
    int gid = lane >> 2, tig = lane & 3;
    int colb = 2 * tig;
    uint sb = smem_u32(dsm);
    int m0 = blockIdx.x * 128;

    // async: agg -> P, Wg -> Q (G1); W1_0 -> R (G2)
    cpa_tile(g_agh + (size_t)m0 * DM, g_agl + (size_t)m0 * DM, 0, 0, DM, sb + P_HI, tid);
    cpa_tile(Wgh, Wgl, 0, 0, DM, sb + Q_HI, tid);
    CP_COMMIT();
    cpa_tile(W1h, W1l, 0, 0, DM, sb + R_HI, tid);
    CP_COMMIT();

    if (tid < DM) { sBg[tid] = bg[tid]; sLng[tid] = lng[tid]; sLnb[tid] = lnb[tid]; sB2[tid] = b2[tid]; }
    for (int i = tid; i < DFF; i += 256) sB1[i] = b1[i];

    uint offA = (uint)((wid * 16 + (lane & 15)) * LDT_B + ((lane >> 4) << 4));
    uint offB = (uint)(((lane & 7) + ((lane >> 4) << 3)) * LDT_B + (((lane >> 3) & 1) << 4));

    // ---- GCN: acc = agg @ Wg --------------------------------------------
    uint hAh[8][4], hAl[8][4];             // first agg A-frags, then hLN frags
    float acc[16][4];
#pragma unroll
    for (int i = 0; i < 16; i++) { acc[i][0] = acc[i][1] = acc[i][2] = acc[i][3] = 0.f; }

    CP_WAIT(1);
    __syncthreads();
#pragma unroll
    for (int ks = 0; ks < 8; ks++) {
        ldsm4(hAh[ks], sb + P_HI + offA + ks * 32);
        ldsm4(hAl[ks], sb + P_LO + offA + ks * 32);
    }
    mma_fullN(hAh, hAl, sb + Q_HI, sb + Q_LO, offB, acc);

    // ---- bias + relu + LayerNorm entirely in registers ------------------
    float s0 = 0.f, s1 = 0.f, q0 = 0.f, q1 = 0.f;
#pragma unroll
    for (int in = 0; in < 16; in++) {
        float2 bb = *reinterpret_cast<const float2*>(&sBg[in * 8 + colb]);
        float v;
        v = fmaxf(acc[in][0] + bb.x, 0.f); acc[in][0] = v; s0 += v; q0 += v * v;
        v = fmaxf(acc[in][1] + bb.y, 0.f); acc[in][1] = v; s0 += v; q0 += v * v;
        v = fmaxf(acc[in][2] + bb.x, 0.f); acc[in][2] = v; s1 += v; q1 += v * v;
        v = fmaxf(acc[in][3] + bb.y, 0.f); acc[in][3] = v; s1 += v; q1 += v * v;
    }
    s0 += __shfl_xor_sync(0xffffffffu, s0, 1); s0 += __shfl_xor_sync(0xffffffffu, s0, 2);
    s1 += __shfl_xor_sync(0xffffffffu, s1, 1); s1 += __shfl_xor_sync(0xffffffffu, s1, 2);
    q0 += __shfl_xor_sync(0xffffffffu, q0, 1); q0 += __shfl_xor_sync(0xffffffffu, q0, 2);
    q1 += __shfl_xor_sync(0xffffffffu, q1, 1); q1 += __shfl_xor_sync(0xffffffffu, q1, 2);
    float mu0 = s0 * (1.f / 128.f), mu1 = s1 * (1.f / 128.f);
    float rs0 = rsqrtf(fmaxf(q0 * (1.f / 128.f) - mu0 * mu0, 0.f) + 1e-5f);
    float rs1 = rsqrtf(fmaxf(q1 * (1.f / 128.f) - mu1 * mu1, 0.f) + 1e-5f);

#pragma unroll
    for (int ks = 0; ks < 8; ks++) {
        int in0 = 2 * ks, in1 = 2 * ks + 1;
        float2 g0 = *reinterpret_cast<const float2*>(&sLng[in0 * 8 + colb]);
        float2 c0 = *reinterpret_cast<const float2*>(&sLnb[in0 * 8 + colb]);
        float2 g1 = *reinterpret_cast<const float2*>(&sLng[in1 * 8 + colb]);
        float2 c1 = *reinterpret_cast<const float2*>(&sLnb[in1 * 8 + colb]);
        pk2split((acc[in0][0] - mu0) * rs0 * g0.x + c0.x,
                 (acc[in0][1] - mu0) * rs0 * g0.y + c0.y, hAh[ks][0], hAl[ks][0]);
        pk2split((acc[in0][2] - mu1) * rs1 * g0.x + c0.x,
                 (acc[in0][3] - mu1) * rs1 * g0.y + c0.y, hAh[ks][1], hAl[ks][1]);
        pk2split((acc[in1][0] - mu0) * rs0 * g1.x + c1.x,
                 (acc[in1][1] - mu0) * rs0 * g1.y + c1.y, hAh[ks][2], hAl[ks][2]);
        pk2split((acc[in1][2] - mu1) * rs1 * g1.x + c1.x,
                 (acc[in1][3] - mu1) * rs1 * g1.y + c1.y, hAh[ks][3], hAl[ks][3]);
    }

    // ---- FFN loop: mid stays in registers -------------------------------
    float acc2[16][4];
#pragma unroll
    for (int i = 0; i < 16; i++) { acc2[i][0] = acc2[i][1] = acc2[i][2] = acc2[i][3] = 0.f; }

    for (int c = 0; c < 4; c++) {
        __syncthreads();                           // Q released (gcn / prior mma2)
        cpa_tile(W2h, W2l, 0, c * 128, DFF, sb + Q_HI, tid);
        CP_COMMIT();
        CP_WAIT(1);                                // W1c resident in R
        __syncthreads();

        float acc1[16][4];
#pragma unroll
        for (int i = 0; i < 16; i++) { acc1[i][0] = acc1[i][1] = acc1[i][2] = acc1[i][3] = 0.f; }
        mma_fullN(hAh, hAl, sb + R_HI, sb + R_LO, offB, acc1);

        // bias + relu -> mid A-fragments (registers only)
        uint mAh[8][4], mAl[8][4];
#pragma unroll
        for (int ks = 0; ks < 8; ks++) {
            int in0 = 2 * ks, in1 = 2 * ks + 1;
            float2 b0 = *reinterpret_cast<const float2*>(&sB1[c * 128 + in0 * 8 + colb]);
            float2 b1v = *reinterpret_cast<const float2*>(&sB1[c * 128 + in1 * 8 + colb]);
            pk2split(fmaxf(acc1[in0][0] + b0.x, 0.f),
                     fmaxf(acc1[in0][1] + b0.y, 0.f), mAh[ks][0], mAl[ks][0]);
            pk2split(fmaxf(acc1[in0][2] + b0.x, 0.f),
                     fmaxf(acc1[in0][3] + b0.y, 0.f), mAh[ks][1], mAl[ks][1]);
            pk2split(fmaxf(acc1[in1][0] + b1v.x, 0.f),
                     fmaxf(acc1[in1][1] + b1v.y, 0.f), mAh[ks][2], mAl[ks][2]);
            pk2split(fmaxf(acc1[in1][2] + b1v.x, 0.f),
                     fmaxf(acc1[in1][3] + b1v.y, 0.f), mAh[ks][3], mAl[ks][3]);
        }

        CP_WAIT(0);                                // W2c resident in Q
        __syncthreads();                           // all warps done with R
        if (c < 3) {
            cpa_tile(W1h, W1l, (c + 1) * 128, 0, DM, sb + R_HI, tid);
            CP_COMMIT();
        }
        mma_fullN(mAh, mAl, sb + Q_HI, sb + Q_LO, offB, acc2);
    }

    // ---- epilogue: h_out = hLN + ffn + b2, straight from registers ------
    int row0 = m0 + wid * 16 + gid, row1 = row0 + 8;
#pragma unroll
    for (int in = 0; in < 16; in++) {
        int col = in * 8 + colb;
        float2 b2v = *reinterpret_cast<const float2*>(&sB2[col]);
        int ks = in >> 1, jb = (in & 1) * 2;
        uint rh0 = hAh[ks][jb],     rl0 = hAl[ks][jb];
        uint rh1 = hAh[ks][jb + 1], rl1 = hAl[ks][jb + 1];
        float v0 = acc2[in][0] + b2v.x + bfu(rh0) + bfu(rl0);
        float v1 = acc2[in][1] + b2v.y + bfu(rh0 >> 16) + bfu(rl0 >> 16);
        uint h2, l2;
        pk2split(v0, v1, h2, l2);
        *reinterpret_cast<uint*>(g_hh + (size_t)row0 * DM + col) = h2;
        *reinterpret_cast<uint*>(g_hl + (size_t)row0 * DM + col) = l2;
        v0 = acc2[in][2] + b2v.x + bfu(rh1) + bfu(rl1);
        v1 = acc2[in][3] + b2v.y + bfu(rh1 >> 16) + bfu(rl1 >> 16);
        pk2split(v0, v1, h2, l2);
        *reinterpret_cast<uint*>(g_hh + (size_t)row1 * DM + col) = h2;
        *reinterpret_cast<uint*>(g_hl + (size_t)row1 * DM + col) = l2;
    }
}

// ---------------------------------------------------------------------------
// K6: readout
// ---------------------------------------------------------------------------
__global__ __launch_bounds__(128) void readout_kernel(const float4* __restrict__ fcw,
                                                      const float* __restrict__ fcb,
                                                      float* __restrict__ out) {
    int w = threadIdx.x >> 5, lane = threadIdx.x & 31;
    int g = blockIdx.x * 4 + w;
    size_t base = (size_t)g * NPG * DM + 4 * lane;
    float4 s = make_float4(0.f, 0.f, 0.f, 0.f);
#pragma unroll
    for (int j = 0; j < NPG; j++) {
        ushort4 hv = *reinterpret_cast<const ushort4*>(g_hh + base + j * DM);
        ushort4 lv = *reinterpret_cast<const ushort4*>(g_hl + base + j * DM);
        s.x += bfu(hv.x) + bfu(lv.x);
        s.y += bfu(hv.y) + bfu(lv.y);
        s.z += bfu(hv.z) + bfu(lv.z);
        s.w += bfu(hv.w) + bfu(lv.w);
    }
    float4 wv = fcw[lane];
    float p = s.x * wv.x + s.y * wv.y + s.z * wv.z + s.w * wv.w;
#pragma unroll
    for (int o = 16; o; o >>= 1) p += __shfl_xor_sync(0xffffffffu, p, o);
    if (lane == 0)
        out[g] = 1.f / (1.f + expf(-(p * (1.f / 9.f) + fcb[0])));
}

// ---------------------------------------------------------------------------
// Launcher
// ---------------------------------------------------------------------------
extern "C" void kernel_launch(void* const* d_in, const int* in_sizes, int n_in,
                              void* d_out, int out_size) {
    const float* op_table   = (const float*)d_in[0];
    const float* device_emb = (const float*)d_in[1];
    const float* Wg         = (const float*)d_in[2];
    const float* bg         = (const float*)d_in[3];
    const float* ln_g       = (const float*)d_in[4];
    const float* ln_b       = (const float*)d_in[5];
    const float* W1         = (const float*)d_in[6];
    const float* b1         = (const float*)d_in[7];
    const float* W2         = (const float*)d_in[8];
    const float* b2         = (const float*)d_in[9];
    const float* fc_w       = (const float*)d_in[10];
    const float* fc_b       = (const float*)d_in[11];
    const int*   op_idx     = (const int*)d_in[12];
    const int*   src        = (const int*)d_in[13];
    const int*   dst        = (const int*)d_in[14];
    float* out = (float*)d_out;

    cudaFuncSetAttribute(layer_mm, cudaFuncAttributeMaxDynamicSharedMemorySize, LM_SMEM);

    ushort *wgh, *wgl, *w1h, *w1l, *w2h, *w2l;
    cudaGetSymbolAddress((void**)&wgh, g_Wgh);
    cudaGetSymbolAddress((void**)&wgl, g_Wgl);
    cudaGetSymbolAddress((void**)&w1h, g_W1h);
    cudaGetSymbolAddress((void**)&w1l, g_W1l);
    cudaGetSymbolAddress((void**)&w2h, g_W2h);
    cudaGetSymbolAddress((void**)&w2l, g_W2l);

    prep_w<<<dim3((DM * DM + 255) / 256, 1, NL), 256>>>(Wg, wgh, wgl, DM, DM);
    prep_w<<<dim3((DM * DFF + 255) / 256, 1, NL), 256>>>(W1, w1h, w1l, DM, DFF);
    prep_w<<<dim3((DM * DFF + 255) / 256, 1, NL), 256>>>(W2, w2h, w2l, DFF, DM);

    deg_kernel<<<BGR / 256, 256>>>(dst);
    embed_kernel<<<(NNODE * 32) / 256, 256>>>(
        (const float4*)op_table, (const float4*)device_emb, op_idx);

    for (int l = 0; l < NL; l++) {
        size_t o1 = (size_t)l * DM * DM, o2 = (size_t)l * DFF * DM, o3 = (size_t)l * DM * DFF;
        agg_kernel<<<BGR, 128>>>(src, dst);
        layer_mm<<<NTILES, 256, LM_SMEM>>>(
            wgh + o1, wgl + o1, w1h + o2, w1l + o2, w2h + o3, w2l + o3,
            bg + l * DM, ln_g + l * DM, ln_b + l * DM, b1 + l * DFF, b2 + l * DM);
    }

    readout_kernel<<<BGR / 4, 128>>>((const float4*)fc_w, fc_b, out);
}

// round 13
// speedup vs baseline: 1.3106x; 1.0009x over previous
#include <cuda_runtime.h>
#include <cuda_bf16.h>
#include <cstdint>
#include <math.h>

typedef unsigned int uint;
typedef unsigned long long ull;
typedef unsigned short ushort;

// ---------------------------------------------------------------------------
// Problem constants
// ---------------------------------------------------------------------------
#define BGR   16384
#define NPG   9
#define NNODE (BGR * NPG)      // 147456
#define DM    128
#define DFF   512
#define NL    4
#define EPG   16

#define NTILES (NNODE / 128)   // 1152

// smem tile geometry: 128 rows x 128 bf16, padded row stride 272 B (17x16B)
#define LDT_B   272
#define TILE_B  (128 * LDT_B)          // 34816

// layer kernel smem: P pair (agg), Q pair (Wg -> W2c), R pair (W1c)
#define P_HI    0
#define P_LO    TILE_B
#define Q_HI    (2 * TILE_B)
#define Q_LO    (3 * TILE_B)
#define R_HI    (4 * TILE_B)
#define R_LO    (5 * TILE_B)
#define LM_SMEM (6 * TILE_B)           // 208896

// ---------------------------------------------------------------------------
// Scratch (device globals) — activations and weights as separate hi/lo
// bf16 planes; value = hi + lo.
// ---------------------------------------------------------------------------
__device__ ushort g_hh [(size_t)NNODE * DM], g_hl [(size_t)NNODE * DM];
__device__ ushort g_agh[(size_t)NNODE * DM], g_agl[(size_t)NNODE * DM];
__device__ float  g_inv[NNODE];
__device__ ushort g_Wgh[(size_t)NL * DM * DM],  g_Wgl[(size_t)NL * DM * DM];
__device__ ushort g_W1h[(size_t)NL * DFF * DM], g_W1l[(size_t)NL * DFF * DM];
__device__ ushort g_W2h[(size_t)NL * DM * DFF], g_W2l[(size_t)NL * DM * DFF];

// ---------------------------------------------------------------------------
// helpers
// ---------------------------------------------------------------------------
__device__ __forceinline__ uint smem_u32(const void* p) {
    uint a;
    asm("{ .reg .u64 t; cvta.to.shared.u64 t, %1; cvt.u32.u64 %0, t; }" : "=r"(a) : "l"(p));
    return a;
}
__device__ __forceinline__ void ldsm4(uint* r, uint addr) {
    asm volatile("ldmatrix.sync.aligned.m8n8.x4.shared.b16 {%0,%1,%2,%3}, [%4];"
        : "=r"(r[0]), "=r"(r[1]), "=r"(r[2]), "=r"(r[3]) : "r"(addr));
}
__device__ __forceinline__ void mma_bf16(float* c, const uint* a, const uint* b) {
    asm volatile("mma.sync.aligned.m16n8k16.row.col.f32.bf16.bf16.f32 "
        "{%0,%1,%2,%3}, {%4,%5,%6,%7}, {%8,%9}, {%0,%1,%2,%3};"
        : "+f"(c[0]), "+f"(c[1]), "+f"(c[2]), "+f"(c[3])
        : "r"(a[0]), "r"(a[1]), "r"(a[2]), "r"(a[3]), "r"(b[0]), "r"(b[1]));
}
__device__ __forceinline__ uint pksplit(float v) {
    __nv_bfloat16 h = __float2bfloat16(v);
    __nv_bfloat16 l = __float2bfloat16(v - __bfloat162float(h));
    return (uint)__bfloat16_as_ushort(h) | ((uint)__bfloat16_as_ushort(l) << 16);
}
__device__ __forceinline__ float bfu(uint s) {
    return __bfloat162float(__ushort_as_bfloat16((ushort)s));
}
// split two adjacent values into packed hi-pair / lo-pair (elem0 in low 16)
__device__ __forceinline__ void pk2split(float v0, float v1, uint &hi2, uint &lo2) {
    asm("cvt.rn.bf16x2.f32 %0, %1, %2;" : "=r"(hi2) : "f"(v1), "f"(v0));
    float h0 = __uint_as_float(hi2 << 16);
    float h1 = __uint_as_float(hi2 & 0xffff0000u);
    float l0 = v0 - h0, l1 = v1 - h1;
    asm("cvt.rn.bf16x2.f32 %0, %1, %2;" : "=r"(lo2) : "f"(l1), "f"(l0));
}

#define CP16(sm, gp) do {                                                     \
    unsigned long long _g;                                                    \
    asm("cvta.to.global.u64 %0, %1;" : "=l"(_g) : "l"(gp));                   \
    asm volatile("cp.async.cg.shared.global [%0], [%1], 16;" :: "r"(sm), "l"(_g)); \
} while (0)
#define CP_COMMIT() asm volatile("cp.async.commit_group;" ::: "memory")
#define CP_WAIT(n)  asm volatile("cp.async.wait_group %0;" :: "n"(n) : "memory")

// async load of a 128x128 bf16 plane pair into (sbase, sbase+TILE_B)
__device__ __forceinline__ void cpa_tile(const ushort* __restrict__ gh,
                                         const ushort* __restrict__ gl,
                                         int row0, int col0, int ldg,
                                         uint sbase, int tid) {
#pragma unroll
    for (int i = 0; i < 8; i++) {
        int idx = tid + 256 * i;       // 2048 granules per plane
        int r = idx >> 4, g = idx & 15;
        uint d = sbase + r * LDT_B + g * 16;
        CP16(d,          gh + (size_t)(row0 + r) * ldg + col0 + g * 8);
        CP16(d + TILE_B, gl + (size_t)(row0 + r) * ldg + col0 + g * 8);
    }
}

// ---------------------------------------------------------------------------
// full-N MMA: warp tile 16(M) x 128(N), A fragments in REGISTERS,
// B tile pair in smem. 3-pass split accumulate (AhBh + AhBl + AlBh).
// B fragments software-pipelined (depth 2) so LDSM latency hides under MMAs.
// ---------------------------------------------------------------------------
__device__ __forceinline__ void ldfragB(uint bHi, uint bLo, uint offB, int it,
                                        uint f[16]) {
    int ks = it >> 2, pp = it & 3;
    uint ob0 = offB + (uint)((2 * pp) * 16 * LDT_B) + (uint)(ks * 32);
    uint ob1 = ob0 + 16 * LDT_B;
    ldsm4(f + 0,  bHi + ob0);
    ldsm4(f + 4,  bLo + ob0);
    ldsm4(f + 8,  bHi + ob1);
    ldsm4(f + 12, bLo + ob1);
}

__device__ __forceinline__ void mma_fullN(const uint aH[8][4], const uint aL[8][4],
                                          uint bHi, uint bLo, uint offB,
                                          float acc[16][4]) {
    uint f[2][16];
    ldfragB(bHi, bLo, offB, 0, f[0]);
#pragma unroll
    for (int it = 0; it < 32; it++) {
        if (it < 31) ldfragB(bHi, bLo, offB, it + 1, f[(it + 1) & 1]);
        const uint* F = f[it & 1];
        int ks = it >> 2, pp = it & 3;
        // F[0..3]=bh0, F[4..7]=bl0, F[8..11]=bh1, F[12..15]=bl1
        mma_bf16(acc[4 * pp + 0], aH[ks], &F[0]);
        mma_bf16(acc[4 * pp + 1], aH[ks], &F[2]);
        mma_bf16(acc[4 * pp + 2], aH[ks], &F[8]);
        mma_bf16(acc[4 * pp + 3], aH[ks], &F[10]);
        mma_bf16(acc[4 * pp + 0], aH[ks], &F[4]);
        mma_bf16(acc[4 * pp + 1], aH[ks], &F[6]);
        mma_bf16(acc[4 * pp + 2], aH[ks], &F[12]);
        mma_bf16(acc[4 * pp + 3], aH[ks], &F[14]);
        mma_bf16(acc[4 * pp + 0], aL[ks], &F[0]);
        mma_bf16(acc[4 * pp + 1], aL[ks], &F[2]);
        mma_bf16(acc[4 * pp + 2], aL[ks], &F[8]);
        mma_bf16(acc[4 * pp + 3], aL[ks], &F[10]);
    }
}

// ---------------------------------------------------------------------------
// K0: degree -> inv_sqrt_deg
// ---------------------------------------------------------------------------
__global__ void deg_kernel(const int* __restrict__ dst) {
    int g = blockIdx.x * blockDim.x + threadIdx.x;
    if (g >= BGR) return;
    int base = g * NPG;
    int cnt[NPG];
#pragma unroll
    for (int j = 0; j < NPG; j++) cnt[j] = 1;
#pragma unroll
    for (int e = 0; e < EPG; e++) {
        int dl = dst[g * EPG + e] - base;
#pragma unroll
        for (int j = 0; j < NPG; j++) cnt[j] += (dl == j) ? 1 : 0;
    }
#pragma unroll
    for (int j = 0; j < NPG; j++)
        g_inv[base + j] = rsqrtf((float)cnt[j]);
}

// ---------------------------------------------------------------------------
// K1: embedding -> h planes
// ---------------------------------------------------------------------------
__global__ void embed_kernel(const float4* __restrict__ opt,
                             const float4* __restrict__ de,
                             const int* __restrict__ op_idx) {
    int idx = blockIdx.x * blockDim.x + threadIdx.x;   // NNODE*32
    int n = idx >> 5, c = idx & 31;
    float4 t = opt[op_idx[n] * 32 + c];
    float4 d = de[c];
    uint h0, l0, h1, l1;
    pk2split(t.x + d.x, t.y + d.y, h0, l0);
    pk2split(t.z + d.z, t.w + d.w, h1, l1);
    size_t o = (size_t)n * DM + 4 * c;
    *reinterpret_cast<uint2*>(g_hh + o) = make_uint2(h0, h1);
    *reinterpret_cast<uint2*>(g_hl + o) = make_uint2(l0, l1);
}

// ---------------------------------------------------------------------------
// K2: per-graph aggregation (planes in / planes out, no atomics)
// ---------------------------------------------------------------------------
__global__ __launch_bounds__(128) void agg_kernel(const int* __restrict__ src,
                                                  const int* __restrict__ dst) {
    __shared__ float hs[NPG * DM];
    __shared__ float ag[NPG * DM];
    __shared__ float invs[NPG];
    __shared__ float we[EPG];
    __shared__ int sl[EPG], dl[EPG];

    int g = blockIdx.x, t = threadIdx.x;
    int nbase = g * NPG;
    if (t < NPG) invs[t] = g_inv[nbase + t];
    if (t < EPG) {
        sl[t] = src[g * EPG + t] - nbase;
        dl[t] = dst[g * EPG + t] - nbase;
    }
    __syncthreads();
    if (t < EPG) we[t] = invs[sl[t]] * invs[dl[t]];
#pragma unroll
    for (int j = 0; j < NPG; j++) {
        size_t o = (size_t)(nbase + j) * DM + t;
        float v = bfu(g_hh[o]) + bfu(g_hl[o]);
        hs[j * DM + t] = v;
        ag[j * DM + t] = invs[j] * invs[j] * v;
    }
    __syncthreads();
#pragma unroll
    for (int e = 0; e < EPG; e++)
        ag[dl[e] * DM + t] += we[e] * hs[sl[e] * DM + t];
#pragma unroll
    for (int j = 0; j < NPG; j++) {
        uint u = pksplit(ag[j * DM + t]);
        size_t o = (size_t)(nbase + j) * DM + t;
        g_agh[o] = (ushort)(u & 0xffffu);
        g_agl[o] = (ushort)(u >> 16);
    }
}

// ---------------------------------------------------------------------------
// Weight prep: planes[c][r] = split(src[r][c])
// ---------------------------------------------------------------------------
__global__ void prep_w(const float* __restrict__ src,
                       ushort* __restrict__ dh, ushort* __restrict__ dl,
                       int R, int C) {
    int l = blockIdx.z;
    src += (size_t)l * R * C;
    dh  += (size_t)l * R * C;
    dl  += (size_t)l * R * C;
    int n = blockIdx.x * blockDim.x + threadIdx.x;
    if (n >= R * C) return;
    int c = n / R, r = n % R;
    uint u = pksplit(src[(size_t)r * C + c]);
    dh[n] = (ushort)(u & 0xffffu);
    dl[n] = (ushort)(u >> 16);
}

// ---------------------------------------------------------------------------
// K3: fused layer GEMMs, register-resident intermediates.
// warp tile 16(M) x 128(N); C-frag of one GEMM feeds A-frag of the next.
// ---------------------------------------------------------------------------
__global__ __launch_bounds__(256) void layer_mm(
    const ushort* __restrict__ Wgh, const ushort* __restrict__ Wgl,
    const ushort* __restrict__ W1h, const ushort* __restrict__ W1l,
    const ushort* __restrict__ W2h, const ushort* __restrict__ W2l,
    const float* __restrict__ bg, const float* __restrict__ lng,
    const float* __restrict__ lnb, const float* __restrict__ b1,
    const float* __restrict__ b2) {

    extern __shared__ char dsm[];
    __shared__ __align__(16) float sBg[DM], sLng[DM], sLnb[DM], sB1[DFF], sB2[DM];

    int tid = threadIdx.x, lane = tid & 31, wid = tid >> 5;
    int gid = lane >> 2, tig = lane & 3;
    int colb = 2 * tig;
    uint sb = smem_u32(dsm);
    int m0 = blockIdx.x * 128;

    // async: agg -> P, Wg -> Q (G1); W1_0 -> R (G2)
    cpa_tile(g_agh + (size_t)m0 * DM, g_agl + (size_t)m0 * DM, 0, 0, DM, sb + P_HI, tid);
    cpa_tile(Wgh, Wgl, 0, 0, DM, sb + Q_HI, tid);
    CP_COMMIT();
    cpa_tile(W1h, W1l, 0, 0, DM, sb + R_HI, tid);
    CP_COMMIT();

    if (tid < DM) { sBg[tid] = bg[tid]; sLng[tid] = lng[tid]; sLnb[tid] = lnb[tid]; sB2[tid] = b2[tid]; }
    for (int i = tid; i < DFF; i += 256) sB1[i] = b1[i];

    uint offA = (uint)((wid * 16 + (lane & 15)) * LDT_B + ((lane >> 4) << 4));
    uint offB = (uint)(((lane & 7) + ((lane >> 4) << 3)) * LDT_B + (((lane >> 3) & 1) << 4));

    // ---- GCN: acc = agg @ Wg --------------------------------------------
    uint hAh[8][4], hAl[8][4];             // first agg A-frags, then hLN frags
    float acc[16][4];
#pragma unroll
    for (int i = 0; i < 16; i++) { acc[i][0] = acc[i][1] = acc[i][2] = acc[i][3] = 0.f; }

    CP_WAIT(1);
    __syncthreads();
#pragma unroll
    for (int ks = 0; ks < 8; ks++) {
        ldsm4(hAh[ks], sb + P_HI + offA + ks * 32);
        ldsm4(hAl[ks], sb + P_LO + offA + ks * 32);
    }
    mma_fullN(hAh, hAl, sb + Q_HI, sb + Q_LO, offB, acc);

    // ---- bias + relu + LayerNorm entirely in registers ------------------
    float s0 = 0.f, s1 = 0.f, q0 = 0.f, q1 = 0.f;
#pragma unroll
    for (int in = 0; in < 16; in++) {
        float2 bb = *reinterpret_cast<const float2*>(&sBg[in * 8 + colb]);
        float v;
        v = fmaxf(acc[in][0] + bb.x, 0.f); acc[in][0] = v; s0 += v; q0 += v * v;
        v = fmaxf(acc[in][1] + bb.y, 0.f); acc[in][1] = v; s0 += v; q0 += v * v;
        v = fmaxf(acc[in][2] + bb.x, 0.f); acc[in][2] = v; s1 += v; q1 += v * v;
        v = fmaxf(acc[in][3] + bb.y, 0.f); acc[in][3] = v; s1 += v; q1 += v * v;
    }
    s0 += __shfl_xor_sync(0xffffffffu, s0, 1); s0 += __shfl_xor_sync(0xffffffffu, s0, 2);
    s1 += __shfl_xor_sync(0xffffffffu, s1, 1); s1 += __shfl_xor_sync(0xffffffffu, s1, 2);
    q0 += __shfl_xor_sync(0xffffffffu, q0, 1); q0 += __shfl_xor_sync(0xffffffffu, q0, 2);
    q1 += __shfl_xor_sync(0xffffffffu, q1, 1); q1 += __shfl_xor_sync(0xffffffffu, q1, 2);
    float mu0 = s0 * (1.f / 128.f), mu1 = s1 * (1.f / 128.f);
    float rs0 = rsqrtf(fmaxf(q0 * (1.f / 128.f) - mu0 * mu0, 0.f) + 1e-5f);
    float rs1 = rsqrtf(fmaxf(q1 * (1.f / 128.f) - mu1 * mu1, 0.f) + 1e-5f);

#pragma unroll
    for (int ks = 0; ks < 8; ks++) {
        int in0 = 2 * ks, in1 = 2 * ks + 1;
        float2 g0 = *reinterpret_cast<const float2*>(&sLng[in0 * 8 + colb]);
        float2 c0 = *reinterpret_cast<const float2*>(&sLnb[in0 * 8 + colb]);
        float2 g1 = *reinterpret_cast<const float2*>(&sLng[in1 * 8 + colb]);
        float2 c1 = *reinterpret_cast<const float2*>(&sLnb[in1 * 8 + colb]);
        pk2split((acc[in0][0] - mu0) * rs0 * g0.x + c0.x,
                 (acc[in0][1] - mu0) * rs0 * g0.y + c0.y, hAh[ks][0], hAl[ks][0]);
        pk2split((acc[in0][2] - mu1) * rs1 * g0.x + c0.x,
                 (acc[in0][3] - mu1) * rs1 * g0.y + c0.y, hAh[ks][1], hAl[ks][1]);
        pk2split((acc[in1][0] - mu0) * rs0 * g1.x + c1.x,
                 (acc[in1][1] - mu0) * rs0 * g1.y + c1.y, hAh[ks][2], hAl[ks][2]);
        pk2split((acc[in1][2] - mu1) * rs1 * g1.x + c1.x,
                 (acc[in1][3] - mu1) * rs1 * g1.y + c1.y, hAh[ks][3], hAl[ks][3]);
    }

    // ---- FFN loop: mid stays in registers -------------------------------
    float acc2[16][4];
#pragma unroll
    for (int i = 0; i < 16; i++) { acc2[i][0] = acc2[i][1] = acc2[i][2] = acc2[i][3] = 0.f; }

    for (int c = 0; c < 4; c++) {
        __syncthreads();                           // Q released (gcn / prior mma2)
        cpa_tile(W2h, W2l, 0, c * 128, DFF, sb + Q_HI, tid);
        CP_COMMIT();
        CP_WAIT(1);                                // W1c resident in R
        __syncthreads();

        float acc1[16][4];
#pragma unroll
        for (int i = 0; i < 16; i++) { acc1[i][0] = acc1[i][1] = acc1[i][2] = acc1[i][3] = 0.f; }
        mma_fullN(hAh, hAl, sb + R_HI, sb + R_LO, offB, acc1);

        // bias + relu -> mid A-fragments (registers only)
        uint mAh[8][4], mAl[8][4];
#pragma unroll
        for (int ks = 0; ks < 8; ks++) {
            int in0 = 2 * ks, in1 = 2 * ks + 1;
            float2 b0 = *reinterpret_cast<const float2*>(&sB1[c * 128 + in0 * 8 + colb]);
            float2 b1v = *reinterpret_cast<const float2*>(&sB1[c * 128 + in1 * 8 + colb]);
            pk2split(fmaxf(acc1[in0][0] + b0.x, 0.f),
                     fmaxf(acc1[in0][1] + b0.y, 0.f), mAh[ks][0], mAl[ks][0]);
            pk2split(fmaxf(acc1[in0][2] + b0.x, 0.f),
                     fmaxf(acc1[in0][3] + b0.y, 0.f), mAh[ks][1], mAl[ks][1]);
            pk2split(fmaxf(acc1[in1][0] + b1v.x, 0.f),
                     fmaxf(acc1[in1][1] + b1v.y, 0.f), mAh[ks][2], mAl[ks][2]);
            pk2split(fmaxf(acc1[in1][2] + b1v.x, 0.f),
                     fmaxf(acc1[in1][3] + b1v.y, 0.f), mAh[ks][3], mAl[ks][3]);
        }

        CP_WAIT(0);                                // W2c resident in Q
        __syncthreads();                           // all warps done with R
        if (c < 3) {
            cpa_tile(W1h, W1l, (c + 1) * 128, 0, DM, sb + R_HI, tid);
            CP_COMMIT();
        }
        mma_fullN(mAh, mAl, sb + Q_HI, sb + Q_LO, offB, acc2);
    }

    // ---- epilogue: h_out = hLN + ffn + b2, straight from registers ------
    int row0 = m0 + wid * 16 + gid, row1 = row0 + 8;
#pragma unroll
    for (int in = 0; in < 16; in++) {
        int col = in * 8 + colb;
        float2 b2v = *reinterpret_cast<const float2*>(&sB2[col]);
        int ks = in >> 1, jb = (in & 1) * 2;
        uint rh0 = hAh[ks][jb],     rl0 = hAl[ks][jb];
        uint rh1 = hAh[ks][jb + 1], rl1 = hAl[ks][jb + 1];
        float v0 = acc2[in][0] + b2v.x + bfu(rh0) + bfu(rl0);
        float v1 = acc2[in][1] + b2v.y + bfu(rh0 >> 16) + bfu(rl0 >> 16);
        uint h2, l2;
        pk2split(v0, v1, h2, l2);
        *reinterpret_cast<uint*>(g_hh + (size_t)row0 * DM + col) = h2;
        *reinterpret_cast<uint*>(g_hl + (size_t)row0 * DM + col) = l2;
        v0 = acc2[in][2] + b2v.x + bfu(rh1) + bfu(rl1);
        v1 = acc2[in][3] + b2v.y + bfu(rh1 >> 16) + bfu(rl1 >> 16);
        pk2split(v0, v1, h2, l2);
        *reinterpret_cast<uint*>(g_hh + (size_t)row1 * DM + col) = h2;
        *reinterpret_cast<uint*>(g_hl + (size_t)row1 * DM + col) = l2;
    }
}

// ---------------------------------------------------------------------------
// K6: readout
// ---------------------------------------------------------------------------
__global__ __launch_bounds__(128) void readout_kernel(const float4* __restrict__ fcw,
                                                      const float* __restrict__ fcb,
                                                      float* __restrict__ out) {
    int w = threadIdx.x >> 5, lane = threadIdx.x & 31;
    int g = blockIdx.x * 4 + w;
    size_t base = (size_t)g * NPG * DM + 4 * lane;
    float4 s = make_float4(0.f, 0.f, 0.f, 0.f);
#pragma unroll
    for (int j = 0; j < NPG; j++) {
        ushort4 hv = *reinterpret_cast<const ushort4*>(g_hh + base + j * DM);
        ushort4 lv = *reinterpret_cast<const ushort4*>(g_hl + base + j * DM);
        s.x += bfu(hv.x) + bfu(lv.x);
        s.y += bfu(hv.y) + bfu(lv.y);
        s.z += bfu(hv.z) + bfu(lv.z);
        s.w += bfu(hv.w) + bfu(lv.w);
    }
    float4 wv = fcw[lane];
    float p = s.x * wv.x + s.y * wv.y + s.z * wv.z + s.w * wv.w;
#pragma unroll
    for (int o = 16; o; o >>= 1) p += __shfl_xor_sync(0xffffffffu, p, o);
    if (lane == 0)
        out[g] = 1.f / (1.f + expf(-(p * (1.f / 9.f) + fcb[0])));
}

// ---------------------------------------------------------------------------
// Launcher
// ---------------------------------------------------------------------------
extern "C" void kernel_launch(void* const* d_in, const int* in_sizes, int n_in,
                              void* d_out, int out_size) {
    const float* op_table   = (const float*)d_in[0];
    const float* device_emb = (const float*)d_in[1];
    const float* Wg         = (const float*)d_in[2];
    const float* bg         = (const float*)d_in[3];
    const float* ln_g       = (const float*)d_in[4];
    const float* ln_b       = (const float*)d_in[5];
    const float* W1         = (const float*)d_in[6];
    const float* b1         = (const float*)d_in[7];
    const float* W2         = (const float*)d_in[8];
    const float* b2         = (const float*)d_in[9];
    const float* fc_w       = (const float*)d_in[10];
    const float* fc_b       = (const float*)d_in[11];
    const int*   op_idx     = (const int*)d_in[12];
    const int*   src        = (const int*)d_in[13];
    const int*   dst        = (const int*)d_in[14];
    float* out = (float*)d_out;

    cudaFuncSetAttribute(layer_mm, cudaFuncAttributeMaxDynamicSharedMemorySize, LM_SMEM);

    ushort *wgh, *wgl, *w1h, *w1l, *w2h, *w2l;
    cudaGetSymbolAddress((void**)&wgh, g_Wgh);
    cudaGetSymbolAddress((void**)&wgl, g_Wgl);
    cudaGetSymbolAddress((void**)&w1h, g_W1h);
    cudaGetSymbolAddress((void**)&w1l, g_W1l);
    cudaGetSymbolAddress((void**)&w2h, g_W2h);
    cudaGetSymbolAddress((void**)&w2l, g_W2l);

    prep_w<<<dim3((DM * DM + 255) / 256, 1, NL), 256>>>(Wg, wgh, wgl, DM, DM);
    prep_w<<<dim3((DM * DFF + 255) / 256, 1, NL), 256>>>(W1, w1h, w1l, DM, DFF);
    prep_w<<<dim3((DM * DFF + 255) / 256, 1, NL), 256>>>(W2, w2h, w2l, DFF, DM);

    deg_kernel<<<BGR / 256, 256>>>(dst);
    embed_kernel<<<(NNODE * 32) / 256, 256>>>(
        (const float4*)op_table, (const float4*)device_emb, op_idx);

    for (int l = 0; l < NL; l++) {
        size_t o1 = (size_t)l * DM * DM, o2 = (size_t)l * DFF * DM, o3 = (size_t)l * DM * DFF;
        agg_kernel<<<BGR, 128>>>(src, dst);
        layer_mm<<<NTILES, 256, LM_SMEM>>>(
            wgh + o1, wgl + o1, w1h + o2, w1l + o2, w2h + o3, w2l + o3,
            bg + l * DM, ln_g + l * DM, ln_b + l * DM, b1 + l * DFF, b2 + l * DM);
    }

    readout_kernel<<<BGR / 4, 128>>>((const float4*)fc_w, fc_b, out);
}

// round 14
// speedup vs baseline: 1.8953x; 1.4461x over previous
#include <cuda_runtime.h>
#include <cuda_fp16.h>
#include <cstdint>
#include <math.h>

typedef unsigned int uint;
typedef unsigned long long ull;
typedef unsigned short ushort;

// ---------------------------------------------------------------------------
// Problem constants
// ---------------------------------------------------------------------------
#define BGR   16384
#define NPG   9
#define NNODE (BGR * NPG)      // 147456
#define DM    128
#define DFF   512
#define NL    4
#define EPG   16

#define NTILES (NNODE / 128)   // 1152

// smem tile geometry: 128 rows x 128 fp16, padded row stride 272 B (17x16B)
#define LDT_B   272
#define TILE_B  (128 * LDT_B)          // 34816

// layer kernel smem: P (activations, 1 plane), Q pair (Wg->W2c), R pair (W1c)
#define P_HI    0
#define Q_HI    (1 * TILE_B)
#define Q_LO    (2 * TILE_B)
#define R_HI    (3 * TILE_B)
#define R_LO    (4 * TILE_B)
#define LM_SMEM (5 * TILE_B)           // 174080

// fp16 2^-11 as packed half2 (exp bias 15: 15-11=4 -> 0x1000)
#define SC_DN 0x10001000u

// ---------------------------------------------------------------------------
// Scratch — activations: SINGLE fp16 plane. Weights: {hi, lo*2^11} fp16 planes.
// ---------------------------------------------------------------------------
__device__ ushort g_hh [(size_t)NNODE * DM];
__device__ ushort g_agh[(size_t)NNODE * DM];
__device__ float  g_inv[NNODE];
__device__ ushort g_Wgh[(size_t)NL * DM * DM],  g_Wgl[(size_t)NL * DM * DM];
__device__ ushort g_W1h[(size_t)NL * DFF * DM], g_W1l[(size_t)NL * DFF * DM];
__device__ ushort g_W2h[(size_t)NL * DM * DFF], g_W2l[(size_t)NL * DM * DFF];

// ---------------------------------------------------------------------------
// helpers
// ---------------------------------------------------------------------------
__device__ __forceinline__ uint smem_u32(const void* p) {
    uint a;
    asm("{ .reg .u64 t; cvta.to.shared.u64 t, %1; cvt.u32.u64 %0, t; }" : "=r"(a) : "l"(p));
    return a;
}
__device__ __forceinline__ void ldsm4(uint* r, uint addr) {
    asm volatile("ldmatrix.sync.aligned.m8n8.x4.shared.b16 {%0,%1,%2,%3}, [%4];"
        : "=r"(r[0]), "=r"(r[1]), "=r"(r[2]), "=r"(r[3]) : "r"(addr));
}
__device__ __forceinline__ void mma_f16(float* c, const uint* a, const uint* b) {
    asm volatile("mma.sync.aligned.m16n8k16.row.col.f32.f16.f16.f32 "
        "{%0,%1,%2,%3}, {%4,%5,%6,%7}, {%8,%9}, {%0,%1,%2,%3};"
        : "+f"(c[0]), "+f"(c[1]), "+f"(c[2]), "+f"(c[3])
        : "r"(a[0]), "r"(a[1]), "r"(a[2]), "r"(a[3]), "r"(b[0]), "r"(b[1]));
}
// pack two floats into fp16x2 (elem0 in low half)
__device__ __forceinline__ uint pk2f16(float v0, float v1) {
    uint r;
    asm("cvt.rn.f16x2.f32 %0, %1, %2;" : "=r"(r) : "f"(v1), "f"(v0));
    return r;
}
__device__ __forceinline__ float f16f(uint bits16) {
    float f;
    asm("cvt.f32.f16 %0, %1;" : "=f"(f) : "h"((ushort)bits16));
    return f;
}
// half2 scale by 2^-11
__device__ __forceinline__ uint hscale(uint x) {
    uint r;
    asm("mul.rn.f16x2 %0, %1, %2;" : "=r"(r) : "r"(x), "r"(SC_DN));
    return r;
}

#define CP16(sm, gp) do {                                                     \
    unsigned long long _g;                                                    \
    asm("cvta.to.global.u64 %0, %1;" : "=l"(_g) : "l"(gp));                   \
    asm volatile("cp.async.cg.shared.global [%0], [%1], 16;" :: "r"(sm), "l"(_g)); \
} while (0)
#define CP_COMMIT() asm volatile("cp.async.commit_group;" ::: "memory")
#define CP_WAIT(n)  asm volatile("cp.async.wait_group %0;" :: "n"(n) : "memory")

// async load of one 128x128 fp16 plane
__device__ __forceinline__ void cpa_tile1(const ushort* __restrict__ gp,
                                          int row0, int col0, int ldg,
                                          uint sbase, int tid) {
#pragma unroll
    for (int i = 0; i < 8; i++) {
        int idx = tid + 256 * i;
        int r = idx >> 4, g = idx & 15;
        CP16(sbase + r * LDT_B + g * 16, gp + (size_t)(row0 + r) * ldg + col0 + g * 8);
    }
}
// async load of a hi/lo plane pair into (sbase, sbase+TILE_B)
__device__ __forceinline__ void cpa_tile2(const ushort* __restrict__ gh,
                                          const ushort* __restrict__ gl,
                                          int row0, int col0, int ldg,
                                          uint sbase, int tid) {
#pragma unroll
    for (int i = 0; i < 8; i++) {
        int idx = tid + 256 * i;
        int r = idx >> 4, g = idx & 15;
        uint d = sbase + r * LDT_B + g * 16;
        CP16(d,          gh + (size_t)(row0 + r) * ldg + col0 + g * 8);
        CP16(d + TILE_B, gl + (size_t)(row0 + r) * ldg + col0 + g * 8);
    }
}

// ---------------------------------------------------------------------------
// full-N MMA: warp tile 16(M) x 128(N). 2-pass: aH.Bh + (aH*2^-11).(Bl*2^11).
// B fragments depth-2 pipelined.
// ---------------------------------------------------------------------------
__device__ __forceinline__ void ldfragB(uint bHi, uint bLo, uint offB, int it,
                                        uint f[16]) {
    int ks = it >> 2, pp = it & 3;
    uint ob0 = offB + (uint)((2 * pp) * 16 * LDT_B) + (uint)(ks * 32);
    uint ob1 = ob0 + 16 * LDT_B;
    ldsm4(f + 0,  bHi + ob0);
    ldsm4(f + 4,  bLo + ob0);
    ldsm4(f + 8,  bHi + ob1);
    ldsm4(f + 12, bLo + ob1);
}

__device__ __forceinline__ void mma_fullN(const uint aH[8][4], const uint aS[8][4],
                                          uint bHi, uint bLo, uint offB,
                                          float acc[16][4]) {
    uint f[2][16];
    ldfragB(bHi, bLo, offB, 0, f[0]);
#pragma unroll
    for (int it = 0; it < 32; it++) {
        if (it < 31) ldfragB(bHi, bLo, offB, it + 1, f[(it + 1) & 1]);
        const uint* F = f[it & 1];
        int ks = it >> 2, pp = it & 3;
        // F[0..3]=bh0, F[4..7]=bls0, F[8..11]=bh1, F[12..15]=bls1
        mma_f16(acc[4 * pp + 0], aH[ks], &F[0]);
        mma_f16(acc[4 * pp + 1], aH[ks], &F[2]);
        mma_f16(acc[4 * pp + 2], aH[ks], &F[8]);
        mma_f16(acc[4 * pp + 3], aH[ks], &F[10]);
        mma_f16(acc[4 * pp + 0], aS[ks], &F[4]);
        mma_f16(acc[4 * pp + 1], aS[ks], &F[6]);
        mma_f16(acc[4 * pp + 2], aS[ks], &F[12]);
        mma_f16(acc[4 * pp + 3], aS[ks], &F[14]);
    }
}

// ---------------------------------------------------------------------------
// K0: degree -> inv_sqrt_deg
// ---------------------------------------------------------------------------
__global__ void deg_kernel(const int* __restrict__ dst) {
    int g = blockIdx.x * blockDim.x + threadIdx.x;
    if (g >= BGR) return;
    int base = g * NPG;
    int cnt[NPG];
#pragma unroll
    for (int j = 0; j < NPG; j++) cnt[j] = 1;
#pragma unroll
    for (int e = 0; e < EPG; e++) {
        int dl = dst[g * EPG + e] - base;
#pragma unroll
        for (int j = 0; j < NPG; j++) cnt[j] += (dl == j) ? 1 : 0;
    }
#pragma unroll
    for (int j = 0; j < NPG; j++)
        g_inv[base + j] = rsqrtf((float)cnt[j]);
}

// ---------------------------------------------------------------------------
// K1: embedding -> fp16 h plane
// ---------------------------------------------------------------------------
__global__ void embed_kernel(const float4* __restrict__ opt,
                             const float4* __restrict__ de,
                             const int* __restrict__ op_idx) {
    int idx = blockIdx.x * blockDim.x + threadIdx.x;   // NNODE*32
    int n = idx >> 5, c = idx & 31;
    float4 t = opt[op_idx[n] * 32 + c];
    float4 d = de[c];
    uint u0 = pk2f16(t.x + d.x, t.y + d.y);
    uint u1 = pk2f16(t.z + d.z, t.w + d.w);
    *reinterpret_cast<uint2*>(g_hh + (size_t)n * DM + 4 * c) = make_uint2(u0, u1);
}

// ---------------------------------------------------------------------------
// K2: per-graph aggregation (fp16 plane in / out, no atomics)
// ---------------------------------------------------------------------------
__global__ __launch_bounds__(128) void agg_kernel(const int* __restrict__ src,
                                                  const int* __restrict__ dst) {
    __shared__ float hs[NPG * DM];
    __shared__ float ag[NPG * DM];
    __shared__ float invs[NPG];
    __shared__ float we[EPG];
    __shared__ int sl[EPG], dl[EPG];

    int g = blockIdx.x, t = threadIdx.x;
    int nbase = g * NPG;
    if (t < NPG) invs[t] = g_inv[nbase + t];
    if (t < EPG) {
        sl[t] = src[g * EPG + t] - nbase;
        dl[t] = dst[g * EPG + t] - nbase;
    }
    __syncthreads();
    if (t < EPG) we[t] = invs[sl[t]] * invs[dl[t]];
#pragma unroll
    for (int j = 0; j < NPG; j++) {
        float v = f16f(g_hh[(size_t)(nbase + j) * DM + t]);
        hs[j * DM + t] = v;
        ag[j * DM + t] = invs[j] * invs[j] * v;
    }
    __syncthreads();
#pragma unroll
    for (int e = 0; e < EPG; e++)
        ag[dl[e] * DM + t] += we[e] * hs[sl[e] * DM + t];
#pragma unroll
    for (int j = 0; j < NPG; j++) {
        uint u = pk2f16(ag[j * DM + t], 0.f);
        g_agh[(size_t)(nbase + j) * DM + t] = (ushort)(u & 0xffffu);
    }
}

// ---------------------------------------------------------------------------
// Weight prep: planes[c][r] = { fp16(w), fp16((w - fp16(w)) * 2^11) }
// ---------------------------------------------------------------------------
__global__ void prep_w(const float* __restrict__ src,
                       ushort* __restrict__ dh, ushort* __restrict__ dl,
                       int R, int C) {
    int l = blockIdx.z;
    src += (size_t)l * R * C;
    dh  += (size_t)l * R * C;
    dl  += (size_t)l * R * C;
    int n = blockIdx.x * blockDim.x + threadIdx.x;
    if (n >= R * C) return;
    int c = n / R, r = n % R;
    float x = src[(size_t)r * C + c];
    uint h = pk2f16(x, 0.f) & 0xffffu;
    float lo = x - f16f(h);
    uint ls = pk2f16(lo * 2048.f, 0.f) & 0xffffu;
    dh[n] = (ushort)h;
    dl[n] = (ushort)ls;
}

// ---------------------------------------------------------------------------
// K3: fused layer GEMMs, register-resident intermediates, fp16 2-pass.
// ---------------------------------------------------------------------------
__global__ __launch_bounds__(256) void layer_mm(
    const ushort* __restrict__ Wgh, const ushort* __restrict__ Wgl,
    const ushort* __restrict__ W1h, const ushort* __restrict__ W1l,
    const ushort* __restrict__ W2h, const ushort* __restrict__ W2l,
    const float* __restrict__ bg, const float* __restrict__ lng,
    const float* __restrict__ lnb, const float* __restrict__ b1,
    const float* __restrict__ b2) {

    extern __shared__ char dsm[];
    __shared__ __align__(16) float sBg[DM], sLng[DM], sLnb[DM], sB1[DFF], sB2[DM];

    int tid = threadIdx.x, lane = tid & 31, wid = tid >> 5;
    int gid = lane >> 2, tig = lane & 3;
    int colb = 2 * tig;
    uint sb = smem_u32(dsm);
    int m0 = blockIdx.x * 128;

    // async: agg -> P, Wg pair -> Q (G1); W1_0 pair -> R (G2)
    cpa_tile1(g_agh + (size_t)m0 * DM, 0, 0, DM, sb + P_HI, tid);
    cpa_tile2(Wgh, Wgl, 0, 0, DM, sb + Q_HI, tid);
    CP_COMMIT();
    cpa_tile2(W1h, W1l, 0, 0, DM, sb + R_HI, tid);
    CP_COMMIT();

    if (tid < DM) { sBg[tid] = bg[tid]; sLng[tid] = lng[tid]; sLnb[tid] = lnb[tid]; sB2[tid] = b2[tid]; }
    for (int i = tid; i < DFF; i += 256) sB1[i] = b1[i];

    uint offA = (uint)((wid * 16 + (lane & 15)) * LDT_B + ((lane >> 4) << 4));
    uint offB = (uint)(((lane & 7) + ((lane >> 4) << 3)) * LDT_B + (((lane >> 3) & 1) << 4));

    // ---- GCN: acc = agg @ Wg --------------------------------------------
    uint hAh[8][4], hAs[8][4];
    float acc[16][4];
#pragma unroll
    for (int i = 0; i < 16; i++) { acc[i][0] = acc[i][1] = acc[i][2] = acc[i][3] = 0.f; }

    CP_WAIT(1);
    __syncthreads();
#pragma unroll
    for (int ks = 0; ks < 8; ks++) {
        ldsm4(hAh[ks], sb + P_HI + offA + ks * 32);
#pragma unroll
        for (int j = 0; j < 4; j++) hAs[ks][j] = hscale(hAh[ks][j]);
    }
    mma_fullN(hAh, hAs, sb + Q_HI, sb + Q_LO, offB, acc);

    // ---- bias + relu + LayerNorm entirely in registers ------------------
    float s0 = 0.f, s1 = 0.f, q0 = 0.f, q1 = 0.f;
#pragma unroll
    for (int in = 0; in < 16; in++) {
        float2 bb = *reinterpret_cast<const float2*>(&sBg[in * 8 + colb]);
        float v;
        v = fmaxf(acc[in][0] + bb.x, 0.f); acc[in][0] = v; s0 += v; q0 += v * v;
        v = fmaxf(acc[in][1] + bb.y, 0.f); acc[in][1] = v; s0 += v; q0 += v * v;
        v = fmaxf(acc[in][2] + bb.x, 0.f); acc[in][2] = v; s1 += v; q1 += v * v;
        v = fmaxf(acc[in][3] + bb.y, 0.f); acc[in][3] = v; s1 += v; q1 += v * v;
    }
    s0 += __shfl_xor_sync(0xffffffffu, s0, 1); s0 += __shfl_xor_sync(0xffffffffu, s0, 2);
    s1 += __shfl_xor_sync(0xffffffffu, s1, 1); s1 += __shfl_xor_sync(0xffffffffu, s1, 2);
    q0 += __shfl_xor_sync(0xffffffffu, q0, 1); q0 += __shfl_xor_sync(0xffffffffu, q0, 2);
    q1 += __shfl_xor_sync(0xffffffffu, q1, 1); q1 += __shfl_xor_sync(0xffffffffu, q1, 2);
    float mu0 = s0 * (1.f / 128.f), mu1 = s1 * (1.f / 128.f);
    float rs0 = rsqrtf(fmaxf(q0 * (1.f / 128.f) - mu0 * mu0, 0.f) + 1e-5f);
    float rs1 = rsqrtf(fmaxf(q1 * (1.f / 128.f) - mu1 * mu1, 0.f) + 1e-5f);

#pragma unroll
    for (int ks = 0; ks < 8; ks++) {
        int in0 = 2 * ks, in1 = 2 * ks + 1;
        float2 g0 = *reinterpret_cast<const float2*>(&sLng[in0 * 8 + colb]);
        float2 c0 = *reinterpret_cast<const float2*>(&sLnb[in0 * 8 + colb]);
        float2 g1 = *reinterpret_cast<const float2*>(&sLng[in1 * 8 + colb]);
        float2 c1 = *reinterpret_cast<const float2*>(&sLnb[in1 * 8 + colb]);
        hAh[ks][0] = pk2f16((acc[in0][0] - mu0) * rs0 * g0.x + c0.x,
                            (acc[in0][1] - mu0) * rs0 * g0.y + c0.y);
        hAh[ks][1] = pk2f16((acc[in0][2] - mu1) * rs1 * g0.x + c0.x,
                            (acc[in0][3] - mu1) * rs1 * g0.y + c0.y);
        hAh[ks][2] = pk2f16((acc[in1][0] - mu0) * rs0 * g1.x + c1.x,
                            (acc[in1][1] - mu0) * rs0 * g1.y + c1.y);
        hAh[ks][3] = pk2f16((acc[in1][2] - mu1) * rs1 * g1.x + c1.x,
                            (acc[in1][3] - mu1) * rs1 * g1.y + c1.y);
#pragma unroll
        for (int j = 0; j < 4; j++) hAs[ks][j] = hscale(hAh[ks][j]);
    }

    // ---- FFN loop: mid stays in registers -------------------------------
    float acc2[16][4];
#pragma unroll
    for (int i = 0; i < 16; i++) { acc2[i][0] = acc2[i][1] = acc2[i][2] = acc2[i][3] = 0.f; }

    for (int c = 0; c < 4; c++) {
        __syncthreads();                           // Q released
        cpa_tile2(W2h, W2l, 0, c * 128, DFF, sb + Q_HI, tid);
        CP_COMMIT();
        CP_WAIT(1);                                // W1c resident in R
        __syncthreads();

        float acc1[16][4];
#pragma unroll
        for (int i = 0; i < 16; i++) { acc1[i][0] = acc1[i][1] = acc1[i][2] = acc1[i][3] = 0.f; }
        mma_fullN(hAh, hAs, sb + R_HI, sb + R_LO, offB, acc1);

        // bias + relu -> mid A-fragments (registers only)
        uint mAh[8][4], mAs[8][4];
#pragma unroll
        for (int ks = 0; ks < 8; ks++) {
            int in0 = 2 * ks, in1 = 2 * ks + 1;
            float2 b0 = *reinterpret_cast<const float2*>(&sB1[c * 128 + in0 * 8 + colb]);
            float2 b1v = *reinterpret_cast<const float2*>(&sB1[c * 128 + in1 * 8 + colb]);
            mAh[ks][0] = pk2f16(fmaxf(acc1[in0][0] + b0.x, 0.f),
                                fmaxf(acc1[in0][1] + b0.y, 0.f));
            mAh[ks][1] = pk2f16(fmaxf(acc1[in0][2] + b0.x, 0.f),
                                fmaxf(acc1[in0][3] + b0.y, 0.f));
            mAh[ks][2] = pk2f16(fmaxf(acc1[in1][0] + b1v.x, 0.f),
                                fmaxf(acc1[in1][1] + b1v.y, 0.f));
            mAh[ks][3] = pk2f16(fmaxf(acc1[in1][2] + b1v.x, 0.f),
                                fmaxf(acc1[in1][3] + b1v.y, 0.f));
#pragma unroll
            for (int j = 0; j < 4; j++) mAs[ks][j] = hscale(mAh[ks][j]);
        }

        CP_WAIT(0);                                // W2c resident in Q
        __syncthreads();                           // all warps done with R
        if (c < 3) {
            cpa_tile2(W1h, W1l, (c + 1) * 128, 0, DM, sb + R_HI, tid);
            CP_COMMIT();
        }
        mma_fullN(mAh, mAs, sb + Q_HI, sb + Q_LO, offB, acc2);
    }

    // ---- epilogue: h_out = hLN + ffn + b2, straight from registers ------
    int row0 = m0 + wid * 16 + gid, row1 = row0 + 8;
#pragma unroll
    for (int in = 0; in < 16; in++) {
        int col = in * 8 + colb;
        float2 b2v = *reinterpret_cast<const float2*>(&sB2[col]);
        int ks = in >> 1, jb = (in & 1) * 2;
        uint r0 = hAh[ks][jb], r1 = hAh[ks][jb + 1];
        float v0 = acc2[in][0] + b2v.x + f16f(r0 & 0xffffu);
        float v1 = acc2[in][1] + b2v.y + f16f(r0 >> 16);
        *reinterpret_cast<uint*>(g_hh + (size_t)row0 * DM + col) = pk2f16(v0, v1);
        v0 = acc2[in][2] + b2v.x + f16f(r1 & 0xffffu);
        v1 = acc2[in][3] + b2v.y + f16f(r1 >> 16);
        *reinterpret_cast<uint*>(g_hh + (size_t)row1 * DM + col) = pk2f16(v0, v1);
    }
}

// ---------------------------------------------------------------------------
// K6: readout
// ---------------------------------------------------------------------------
__global__ __launch_bounds__(128) void readout_kernel(const float4* __restrict__ fcw,
                                                      const float* __restrict__ fcb,
                                                      float* __restrict__ out) {
    int w = threadIdx.x >> 5, lane = threadIdx.x & 31;
    int g = blockIdx.x * 4 + w;
    size_t base = (size_t)g * NPG * DM + 4 * lane;
    float4 s = make_float4(0.f, 0.f, 0.f, 0.f);
#pragma unroll
    for (int j = 0; j < NPG; j++) {
        ushort4 hv = *reinterpret_cast<const ushort4*>(g_hh + base + j * DM);
        s.x += f16f(hv.x); s.y += f16f(hv.y); s.z += f16f(hv.z); s.w += f16f(hv.w);
    }
    float4 wv = fcw[lane];
    float p = s.x * wv.x + s.y * wv.y + s.z * wv.z + s.w * wv.w;
#pragma unroll
    for (int o = 16; o; o >>= 1) p += __shfl_xor_sync(0xffffffffu, p, o);
    if (lane == 0)
        out[g] = 1.f / (1.f + expf(-(p * (1.f / 9.f) + fcb[0])));
}

// ---------------------------------------------------------------------------
// Launcher
// ---------------------------------------------------------------------------
extern "C" void kernel_launch(void* const* d_in, const int* in_sizes, int n_in,
                              void* d_out, int out_size) {
    const float* op_table   = (const float*)d_in[0];
    const float* device_emb = (const float*)d_in[1];
    const float* Wg         = (const float*)d_in[2];
    const float* bg         = (const float*)d_in[3];
    const float* ln_g       = (const float*)d_in[4];
    const float* ln_b       = (const float*)d_in[5];
    const float* W1         = (const float*)d_in[6];
    const float* b1         = (const float*)d_in[7];
    const float* W2         = (const float*)d_in[8];
    const float* b2         = (const float*)d_in[9];
    const float* fc_w       = (const float*)d_in[10];
    const float* fc_b       = (const float*)d_in[11];
    const int*   op_idx     = (const int*)d_in[12];
    const int*   src        = (const int*)d_in[13];
    const int*   dst        = (const int*)d_in[14];
    float* out = (float*)d_out;

    cudaFuncSetAttribute(layer_mm, cudaFuncAttributeMaxDynamicSharedMemorySize, LM_SMEM);

    ushort *wgh, *wgl, *w1h, *w1l, *w2h, *w2l;
    cudaGetSymbolAddress((void**)&wgh, g_Wgh);
    cudaGetSymbolAddress((void**)&wgl, g_Wgl);
    cudaGetSymbolAddress((void**)&w1h, g_W1h);
    cudaGetSymbolAddress((void**)&w1l, g_W1l);
    cudaGetSymbolAddress((void**)&w2h, g_W2h);
    cudaGetSymbolAddress((void**)&w2l, g_W2l);

    prep_w<<<dim3((DM * DM + 255) / 256, 1, NL), 256>>>(Wg, wgh, wgl, DM, DM);
    prep_w<<<dim3((DM * DFF + 255) / 256, 1, NL), 256>>>(W1, w1h, w1l, DM, DFF);
    prep_w<<<dim3((DM * DFF + 255) / 256, 1, NL), 256>>>(W2, w2h, w2l, DFF, DM);

    deg_kernel<<<BGR / 256, 256>>>(dst);
    embed_kernel<<<(NNODE * 32) / 256, 256>>>(
        (const float4*)op_table, (const float4*)device_emb, op_idx);

    for (int l = 0; l < NL; l++) {
        size_t o1 = (size_t)l * DM * DM, o2 = (size_t)l * DFF * DM, o3 = (size_t)l * DM * DFF;
        agg_kernel<<<BGR, 128>>>(src, dst);
        layer_mm<<<NTILES, 256, LM_SMEM>>>(
            wgh + o1, wgl + o1, w1h + o2, w1l + o2, w2h + o3, w2l + o3,
            bg + l * DM, ln_g + l * DM, ln_b + l * DM, b1 + l * DFF, b2 + l * DM);
    }

    readout_kernel<<<BGR / 4, 128>>>((const float4*)fc_w, fc_b, out);
}

// round 15
// speedup vs baseline: 2.9910x; 1.5781x over previous
#include <cuda_runtime.h>
#include <cuda_fp16.h>
#include <cstdint>
#include <math.h>

typedef unsigned int uint;
typedef unsigned long long ull;
typedef unsigned short ushort;

// ---------------------------------------------------------------------------
// Problem constants
// ---------------------------------------------------------------------------
#define BGR   16384
#define NPG   9
#define NNODE (BGR * NPG)      // 147456
#define DM    128
#define DFF   512
#define NL    4
#define EPG   16

#define NTILES (NNODE / 128)   // 1152

// smem tile geometry: 128 rows x 128 fp16, padded row stride 272 B (17x16B)
#define LDT_B   272
#define TILE_B  (128 * LDT_B)          // 34816

// layer kernel smem: P (activations), Q (Wg->W2c), R (W1c) — single planes
#define P_O     0
#define Q_O     (1 * TILE_B)
#define R_O     (2 * TILE_B)
#define LM_SMEM (3 * TILE_B)           // 104448

// ---------------------------------------------------------------------------
// Scratch — activations and weights: single fp16 planes.
// ---------------------------------------------------------------------------
__device__ ushort g_hh [(size_t)NNODE * DM];
__device__ ushort g_agh[(size_t)NNODE * DM];
__device__ float  g_inv[NNODE];
__device__ ushort g_Wgh[(size_t)NL * DM * DM];
__device__ ushort g_W1h[(size_t)NL * DFF * DM];
__device__ ushort g_W2h[(size_t)NL * DM * DFF];

// ---------------------------------------------------------------------------
// helpers
// ---------------------------------------------------------------------------
__device__ __forceinline__ uint smem_u32(const void* p) {
    uint a;
    asm("{ .reg .u64 t; cvta.to.shared.u64 t, %1; cvt.u32.u64 %0, t; }" : "=r"(a) : "l"(p));
    return a;
}
__device__ __forceinline__ void ldsm4(uint* r, uint addr) {
    asm volatile("ldmatrix.sync.aligned.m8n8.x4.shared.b16 {%0,%1,%2,%3}, [%4];"
        : "=r"(r[0]), "=r"(r[1]), "=r"(r[2]), "=r"(r[3]) : "r"(addr));
}
__device__ __forceinline__ void mma_f16(float* c, const uint* a, const uint* b) {
    asm volatile("mma.sync.aligned.m16n8k16.row.col.f32.f16.f16.f32 "
        "{%0,%1,%2,%3}, {%4,%5,%6,%7}, {%8,%9}, {%0,%1,%2,%3};"
        : "+f"(c[0]), "+f"(c[1]), "+f"(c[2]), "+f"(c[3])
        : "r"(a[0]), "r"(a[1]), "r"(a[2]), "r"(a[3]), "r"(b[0]), "r"(b[1]));
}
// pack two floats into fp16x2 (elem0 in low half)
__device__ __forceinline__ uint pk2f16(float v0, float v1) {
    uint r;
    asm("cvt.rn.f16x2.f32 %0, %1, %2;" : "=r"(r) : "f"(v1), "f"(v0));
    return r;
}
__device__ __forceinline__ float f16f(uint bits16) {
    float f;
    asm("cvt.f32.f16 %0, %1;" : "=f"(f) : "h"((ushort)bits16));
    return f;
}

#define CP16(sm, gp) do {                                                     \
    unsigned long long _g;                                                    \
    asm("cvta.to.global.u64 %0, %1;" : "=l"(_g) : "l"(gp));                   \
    asm volatile("cp.async.cg.shared.global [%0], [%1], 16;" :: "r"(sm), "l"(_g)); \
} while (0)
#define CP_COMMIT() asm volatile("cp.async.commit_group;" ::: "memory")
#define CP_WAIT(n)  asm volatile("cp.async.wait_group %0;" :: "n"(n) : "memory")

// async load of one 128x128 fp16 plane
__device__ __forceinline__ void cpa_tile1(const ushort* __restrict__ gp,
                                          int row0, int col0, int ldg,
                                          uint sbase, int tid) {
#pragma unroll
    for (int i = 0; i < 8; i++) {
        int idx = tid + 256 * i;
        int r = idx >> 4, g = idx & 15;
        CP16(sbase + r * LDT_B + g * 16, gp + (size_t)(row0 + r) * ldg + col0 + g * 8);
    }
}

// ---------------------------------------------------------------------------
// full-N MMA: warp tile 16(M) x 128(N), single-pass fp16.
// B fragments depth-2 pipelined.
// ---------------------------------------------------------------------------
__device__ __forceinline__ void ldfragB(uint bP, uint offB, int it, uint f[8]) {
    int ks = it >> 2, pp = it & 3;
    uint ob0 = offB + (uint)((2 * pp) * 16 * LDT_B) + (uint)(ks * 32);
    uint ob1 = ob0 + 16 * LDT_B;
    ldsm4(f + 0, bP + ob0);
    ldsm4(f + 4, bP + ob1);
}

__device__ __forceinline__ void mma_fullN(const uint aH[8][4],
                                          uint bP, uint offB,
                                          float acc[16][4]) {
    uint f[2][8];
    ldfragB(bP, offB, 0, f[0]);
#pragma unroll
    for (int it = 0; it < 32; it++) {
        if (it < 31) ldfragB(bP, offB, it + 1, f[(it + 1) & 1]);
        const uint* F = f[it & 1];
        int ks = it >> 2, pp = it & 3;
        mma_f16(acc[4 * pp + 0], aH[ks], &F[0]);
        mma_f16(acc[4 * pp + 1], aH[ks], &F[2]);
        mma_f16(acc[4 * pp + 2], aH[ks], &F[4]);
        mma_f16(acc[4 * pp + 3], aH[ks], &F[6]);
    }
}

// ---------------------------------------------------------------------------
// K0: degree -> inv_sqrt_deg
// ---------------------------------------------------------------------------
__global__ void deg_kernel(const int* __restrict__ dst) {
    int g = blockIdx.x * blockDim.x + threadIdx.x;
    if (g >= BGR) return;
    int base = g * NPG;
    int cnt[NPG];
#pragma unroll
    for (int j = 0; j < NPG; j++) cnt[j] = 1;
#pragma unroll
    for (int e = 0; e < EPG; e++) {
        int dl = dst[g * EPG + e] - base;
#pragma unroll
        for (int j = 0; j < NPG; j++) cnt[j] += (dl == j) ? 1 : 0;
    }
#pragma unroll
    for (int j = 0; j < NPG; j++)
        g_inv[base + j] = rsqrtf((float)cnt[j]);
}

// ---------------------------------------------------------------------------
// K1: embedding -> fp16 h plane
// ---------------------------------------------------------------------------
__global__ void embed_kernel(const float4* __restrict__ opt,
                             const float4* __restrict__ de,
                             const int* __restrict__ op_idx) {
    int idx = blockIdx.x * blockDim.x + threadIdx.x;   // NNODE*32
    int n = idx >> 5, c = idx & 31;
    float4 t = opt[op_idx[n] * 32 + c];
    float4 d = de[c];
    uint u0 = pk2f16(t.x + d.x, t.y + d.y);
    uint u1 = pk2f16(t.z + d.z, t.w + d.w);
    *reinterpret_cast<uint2*>(g_hh + (size_t)n * DM + 4 * c) = make_uint2(u0, u1);
}

// ---------------------------------------------------------------------------
// K2: per-graph aggregation (fp16 plane in / out, no atomics)
// ---------------------------------------------------------------------------
__global__ __launch_bounds__(128) void agg_kernel(const int* __restrict__ src,
                                                  const int* __restrict__ dst) {
    __shared__ float hs[NPG * DM];
    __shared__ float ag[NPG * DM];
    __shared__ float invs[NPG];
    __shared__ float we[EPG];
    __shared__ int sl[EPG], dl[EPG];

    int g = blockIdx.x, t = threadIdx.x;
    int nbase = g * NPG;
    if (t < NPG) invs[t] = g_inv[nbase + t];
    if (t < EPG) {
        sl[t] = src[g * EPG + t] - nbase;
        dl[t] = dst[g * EPG + t] - nbase;
    }
    __syncthreads();
    if (t < EPG) we[t] = invs[sl[t]] * invs[dl[t]];
#pragma unroll
    for (int j = 0; j < NPG; j++) {
        float v = f16f(g_hh[(size_t)(nbase + j) * DM + t]);
        hs[j * DM + t] = v;
        ag[j * DM + t] = invs[j] * invs[j] * v;
    }
    __syncthreads();
#pragma unroll
    for (int e = 0; e < EPG; e++)
        ag[dl[e] * DM + t] += we[e] * hs[sl[e] * DM + t];
#pragma unroll
    for (int j = 0; j < NPG; j++) {
        uint u = pk2f16(ag[j * DM + t], 0.f);
        g_agh[(size_t)(nbase + j) * DM + t] = (ushort)(u & 0xffffu);
    }
}

// ---------------------------------------------------------------------------
// Weight prep: plane[c][r] = fp16(src[r][c])
// ---------------------------------------------------------------------------
__global__ void prep_w(const float* __restrict__ src,
                       ushort* __restrict__ dh, int R, int C) {
    int l = blockIdx.z;
    src += (size_t)l * R * C;
    dh  += (size_t)l * R * C;
    int n = blockIdx.x * blockDim.x + threadIdx.x;
    if (n >= R * C) return;
    int c = n / R, r = n % R;
    dh[n] = (ushort)(pk2f16(src[(size_t)r * C + c], 0.f) & 0xffffu);
}

// ---------------------------------------------------------------------------
// K3: fused layer GEMMs, register-resident intermediates, fp16 single-pass.
// ---------------------------------------------------------------------------
__global__ __launch_bounds__(256) void layer_mm(
    const ushort* __restrict__ Wgh,
    const ushort* __restrict__ W1h,
    const ushort* __restrict__ W2h,
    const float* __restrict__ bg, const float* __restrict__ lng,
    const float* __restrict__ lnb, const float* __restrict__ b1,
    const float* __restrict__ b2) {

    extern __shared__ char dsm[];
    __shared__ __align__(16) float sBg[DM], sLng[DM], sLnb[DM], sB1[DFF], sB2[DM];

    int tid = threadIdx.x, lane = tid & 31, wid = tid >> 5;
    int gid = lane >> 2, tig = lane & 3;
    int colb = 2 * tig;
    uint sb = smem_u32(dsm);
    int m0 = blockIdx.x * 128;

    // async: agg -> P, Wg -> Q (G1); W1_0 -> R (G2)
    cpa_tile1(g_agh + (size_t)m0 * DM, 0, 0, DM, sb + P_O, tid);
    cpa_tile1(Wgh, 0, 0, DM, sb + Q_O, tid);
    CP_COMMIT();
    cpa_tile1(W1h, 0, 0, DM, sb + R_O, tid);
    CP_COMMIT();

    if (tid < DM) { sBg[tid] = bg[tid]; sLng[tid] = lng[tid]; sLnb[tid] = lnb[tid]; sB2[tid] = b2[tid]; }
    for (int i = tid; i < DFF; i += 256) sB1[i] = b1[i];

    uint offA = (uint)((wid * 16 + (lane & 15)) * LDT_B + ((lane >> 4) << 4));
    uint offB = (uint)(((lane & 7) + ((lane >> 4) << 3)) * LDT_B + (((lane >> 3) & 1) << 4));

    // ---- GCN: acc = agg @ Wg --------------------------------------------
    uint hAh[8][4];
    float acc[16][4];
#pragma unroll
    for (int i = 0; i < 16; i++) { acc[i][0] = acc[i][1] = acc[i][2] = acc[i][3] = 0.f; }

    CP_WAIT(1);
    __syncthreads();
#pragma unroll
    for (int ks = 0; ks < 8; ks++)
        ldsm4(hAh[ks], sb + P_O + offA + ks * 32);
    mma_fullN(hAh, sb + Q_O, offB, acc);

    // ---- bias + relu + LayerNorm entirely in registers ------------------
    float s0 = 0.f, s1 = 0.f, q0 = 0.f, q1 = 0.f;
#pragma unroll
    for (int in = 0; in < 16; in++) {
        float2 bb = *reinterpret_cast<const float2*>(&sBg[in * 8 + colb]);
        float v;
        v = fmaxf(acc[in][0] + bb.x, 0.f); acc[in][0] = v; s0 += v; q0 += v * v;
        v = fmaxf(acc[in][1] + bb.y, 0.f); acc[in][1] = v; s0 += v; q0 += v * v;
        v = fmaxf(acc[in][2] + bb.x, 0.f); acc[in][2] = v; s1 += v; q1 += v * v;
        v = fmaxf(acc[in][3] + bb.y, 0.f); acc[in][3] = v; s1 += v; q1 += v * v;
    }
    s0 += __shfl_xor_sync(0xffffffffu, s0, 1); s0 += __shfl_xor_sync(0xffffffffu, s0, 2);
    s1 += __shfl_xor_sync(0xffffffffu, s1, 1); s1 += __shfl_xor_sync(0xffffffffu, s1, 2);
    q0 += __shfl_xor_sync(0xffffffffu, q0, 1); q0 += __shfl_xor_sync(0xffffffffu, q0, 2);
    q1 += __shfl_xor_sync(0xffffffffu, q1, 1); q1 += __shfl_xor_sync(0xffffffffu, q1, 2);
    float mu0 = s0 * (1.f / 128.f), mu1 = s1 * (1.f / 128.f);
    float rs0 = rsqrtf(fmaxf(q0 * (1.f / 128.f) - mu0 * mu0, 0.f) + 1e-5f);
    float rs1 = rsqrtf(fmaxf(q1 * (1.f / 128.f) - mu1 * mu1, 0.f) + 1e-5f);

#pragma unroll
    for (int ks = 0; ks < 8; ks++) {
        int in0 = 2 * ks, in1 = 2 * ks + 1;
        float2 g0 = *reinterpret_cast<const float2*>(&sLng[in0 * 8 + colb]);
        float2 c0 = *reinterpret_cast<const float2*>(&sLnb[in0 * 8 + colb]);
        float2 g1 = *reinterpret_cast<const float2*>(&sLng[in1 * 8 + colb]);
        float2 c1 = *reinterpret_cast<const float2*>(&sLnb[in1 * 8 + colb]);
        hAh[ks][0] = pk2f16((acc[in0][0] - mu0) * rs0 * g0.x + c0.x,
                            (acc[in0][1] - mu0) * rs0 * g0.y + c0.y);
        hAh[ks][1] = pk2f16((acc[in0][2] - mu1) * rs1 * g0.x + c0.x,
                            (acc[in0][3] - mu1) * rs1 * g0.y + c0.y);
        hAh[ks][2] = pk2f16((acc[in1][0] - mu0) * rs0 * g1.x + c1.x,
                            (acc[in1][1] - mu0) * rs0 * g1.y + c1.y);
        hAh[ks][3] = pk2f16((acc[in1][2] - mu1) * rs1 * g1.x + c1.x,
                            (acc[in1][3] - mu1) * rs1 * g1.y + c1.y);
    }

    // ---- FFN loop: mid stays in registers -------------------------------
    float acc2[16][4];
#pragma unroll
    for (int i = 0; i < 16; i++) { acc2[i][0] = acc2[i][1] = acc2[i][2] = acc2[i][3] = 0.f; }

    for (int c = 0; c < 4; c++) {
        __syncthreads();                           // Q released
        cpa_tile1(W2h, 0, c * 128, DFF, sb + Q_O, tid);
        CP_COMMIT();
        CP_WAIT(1);                                // W1c resident in R
        __syncthreads();

        float acc1[16][4];
#pragma unroll
        for (int i = 0; i < 16; i++) { acc1[i][0] = acc1[i][1] = acc1[i][2] = acc1[i][3] = 0.f; }
        mma_fullN(hAh, sb + R_O, offB, acc1);

        // bias + relu -> mid A-fragments (registers only)
        uint mAh[8][4];
#pragma unroll
        for (int ks = 0; ks < 8; ks++) {
            int in0 = 2 * ks, in1 = 2 * ks + 1;
            float2 b0 = *reinterpret_cast<const float2*>(&sB1[c * 128 + in0 * 8 + colb]);
            float2 b1v = *reinterpret_cast<const float2*>(&sB1[c * 128 + in1 * 8 + colb]);
            mAh[ks][0] = pk2f16(fmaxf(acc1[in0][0] + b0.x, 0.f),
                                fmaxf(acc1[in0][1] + b0.y, 0.f));
            mAh[ks][1] = pk2f16(fmaxf(acc1[in0][2] + b0.x, 0.f),
                                fmaxf(acc1[in0][3] + b0.y, 0.f));
            mAh[ks][2] = pk2f16(fmaxf(acc1[in1][0] + b1v.x, 0.f),
                                fmaxf(acc1[in1][1] + b1v.y, 0.f));
            mAh[ks][3] = pk2f16(fmaxf(acc1[in1][2] + b1v.x, 0.f),
                                fmaxf(acc1[in1][3] + b1v.y, 0.f));
        }

        CP_WAIT(0);                                // W2c resident in Q
        __syncthreads();                           // all warps done with R
        if (c < 3) {
            cpa_tile1(W1h, (c + 1) * 128, 0, DM, sb + R_O, tid);
            CP_COMMIT();
        }
        mma_fullN(mAh, sb + Q_O, offB, acc2);
    }

    // ---- epilogue: h_out = hLN + ffn + b2, straight from registers ------
    int row0 = m0 + wid * 16 + gid, row1 = row0 + 8;
#pragma unroll
    for (int in = 0; in < 16; in++) {
        int col = in * 8 + colb;
        float2 b2v = *reinterpret_cast<const float2*>(&sB2[col]);
        int ks = in >> 1, jb = (in & 1) * 2;
        uint r0 = hAh[ks][jb], r1 = hAh[ks][jb + 1];
        float v0 = acc2[in][0] + b2v.x + f16f(r0 & 0xffffu);
        float v1 = acc2[in][1] + b2v.y + f16f(r0 >> 16);
        *reinterpret_cast<uint*>(g_hh + (size_t)row0 * DM + col) = pk2f16(v0, v1);
        v0 = acc2[in][2] + b2v.x + f16f(r1 & 0xffffu);
        v1 = acc2[in][3] + b2v.y + f16f(r1 >> 16);
        *reinterpret_cast<uint*>(g_hh + (size_t)row1 * DM + col) = pk2f16(v0, v1);
    }
}

// ---------------------------------------------------------------------------
// K6: readout
// ---------------------------------------------------------------------------
__global__ __launch_bounds__(128) void readout_kernel(const float4* __restrict__ fcw,
                                                      const float* __restrict__ fcb,
                                                      float* __restrict__ out) {
    int w = threadIdx.x >> 5, lane = threadIdx.x & 31;
    int g = blockIdx.x * 4 + w;
    size_t base = (size_t)g * NPG * DM + 4 * lane;
    float4 s = make_float4(0.f, 0.f, 0.f, 0.f);
#pragma unroll
    for (int j = 0; j < NPG; j++) {
        ushort4 hv = *reinterpret_cast<const ushort4*>(g_hh + base + j * DM);
        s.x += f16f(hv.x); s.y += f16f(hv.y); s.z += f16f(hv.z); s.w += f16f(hv.w);
    }
    float4 wv = fcw[lane];
    float p = s.x * wv.x + s.y * wv.y + s.z * wv.z + s.w * wv.w;
#pragma unroll
    for (int o = 16; o; o >>= 1) p += __shfl_xor_sync(0xffffffffu, p, o);
    if (lane == 0)
        out[g] = 1.f / (1.f + expf(-(p * (1.f / 9.f) + fcb[0])));
}

// ---------------------------------------------------------------------------
// Launcher
// ---------------------------------------------------------------------------
extern "C" void kernel_launch(void* const* d_in, const int* in_sizes, int n_in,
                              void* d_out, int out_size) {
    const float* op_table   = (const float*)d_in[0];
    const float* device_emb = (const float*)d_in[1];
    const float* Wg         = (const float*)d_in[2];
    const float* bg         = (const float*)d_in[3];
    const float* ln_g       = (const float*)d_in[4];
    const float* ln_b       = (const float*)d_in[5];
    const float* W1         = (const float*)d_in[6];
    const float* b1         = (const float*)d_in[7];
    const float* W2         = (const float*)d_in[8];
    const float* b2         = (const float*)d_in[9];
    const float* fc_w       = (const float*)d_in[10];
    const float* fc_b       = (const float*)d_in[11];
    const int*   op_idx     = (const int*)d_in[12];
    const int*   src        = (const int*)d_in[13];
    const int*   dst        = (const int*)d_in[14];
    float* out = (float*)d_out;

    cudaFuncSetAttribute(layer_mm, cudaFuncAttributeMaxDynamicSharedMemorySize, LM_SMEM);

    ushort *wgh, *w1h, *w2h;
    cudaGetSymbolAddress((void**)&wgh, g_Wgh);
    cudaGetSymbolAddress((void**)&w1h, g_W1h);
    cudaGetSymbolAddress((void**)&w2h, g_W2h);

    prep_w<<<dim3((DM * DM + 255) / 256, 1, NL), 256>>>(Wg, wgh, DM, DM);
    prep_w<<<dim3((DM * DFF + 255) / 256, 1, NL), 256>>>(W1, w1h, DM, DFF);
    prep_w<<<dim3((DM * DFF + 255) / 256, 1, NL), 256>>>(W2, w2h, DFF, DM);

    deg_kernel<<<BGR / 256, 256>>>(dst);
    embed_kernel<<<(NNODE * 32) / 256, 256>>>(
        (const float4*)op_table, (const float4*)device_emb, op_idx);

    for (int l = 0; l < NL; l++) {
        size_t o1 = (size_t)l * DM * DM, o2 = (size_t)l * DFF * DM, o3 = (size_t)l * DM * DFF;
        agg_kernel<<<BGR, 128>>>(src, dst);
        layer_mm<<<NTILES, 256, LM_SMEM>>>(
            wgh + o1, w1h + o2, w2h + o3,
            bg + l * DM, ln_g + l * DM, ln_b + l * DM, b1 + l * DFF, b2 + l * DM);
    }

    readout_kernel<<<BGR / 4, 128>>>((const float4*)fc_w, fc_b, out);
}

// round 16
// speedup vs baseline: 3.0785x; 1.0293x over previous
#include <cuda_runtime.h>
#include <cuda_fp16.h>
#include <cstdint>
#include <math.h>

typedef unsigned int uint;
typedef unsigned long long ull;
typedef unsigned short ushort;

// ---------------------------------------------------------------------------
// Problem constants
// ---------------------------------------------------------------------------
#define BGR   16384
#define NPG   9
#define NNODE (BGR * NPG)      // 147456
#define DM    128
#define DFF   512
#define NL    4
#define EPG   16

#define NTILES (NNODE / 128)   // 1152

// smem tile geometry: 128 rows x 128 fp16, padded row stride 272 B (17x16B)
#define LDT_B   272
#define TILE_B  (128 * LDT_B)          // 34816

// layer kernel smem: P (activations), Q (Wg->W2c), R (W1c) — single planes
#define P_O     0
#define Q_O     (1 * TILE_B)
#define R_O     (2 * TILE_B)
#define LM_SMEM (3 * TILE_B)           // 104448

// ---------------------------------------------------------------------------
// Scratch — activations and weights: single fp16 planes.
// ---------------------------------------------------------------------------
__device__ ushort g_hh [(size_t)NNODE * DM];
__device__ ushort g_agh[(size_t)NNODE * DM];
__device__ float  g_inv[NNODE];
__device__ ushort g_Wgh[(size_t)NL * DM * DM];
__device__ ushort g_W1h[(size_t)NL * DFF * DM];
__device__ ushort g_W2h[(size_t)NL * DM * DFF];

// ---------------------------------------------------------------------------
// helpers
// ---------------------------------------------------------------------------
__device__ __forceinline__ uint smem_u32(const void* p) {
    uint a;
    asm("{ .reg .u64 t; cvta.to.shared.u64 t, %1; cvt.u32.u64 %0, t; }" : "=r"(a) : "l"(p));
    return a;
}
__device__ __forceinline__ void ldsm4(uint* r, uint addr) {
    asm volatile("ldmatrix.sync.aligned.m8n8.x4.shared.b16 {%0,%1,%2,%3}, [%4];"
        : "=r"(r[0]), "=r"(r[1]), "=r"(r[2]), "=r"(r[3]) : "r"(addr));
}
__device__ __forceinline__ void mma_f16(float* c, const uint* a, const uint* b) {
    asm volatile("mma.sync.aligned.m16n8k16.row.col.f32.f16.f16.f32 "
        "{%0,%1,%2,%3}, {%4,%5,%6,%7}, {%8,%9}, {%0,%1,%2,%3};"
        : "+f"(c[0]), "+f"(c[1]), "+f"(c[2]), "+f"(c[3])
        : "r"(a[0]), "r"(a[1]), "r"(a[2]), "r"(a[3]), "r"(b[0]), "r"(b[1]));
}
// pack two floats into fp16x2 (elem0 in low half)
__device__ __forceinline__ uint pk2f16(float v0, float v1) {
    uint r;
    asm("cvt.rn.f16x2.f32 %0, %1, %2;" : "=r"(r) : "f"(v1), "f"(v0));
    return r;
}
__device__ __forceinline__ float f16f(uint bits16) {
    float f;
    asm("cvt.f32.f16 %0, %1;" : "=f"(f) : "h"((ushort)bits16));
    return f;
}

#define CP16(sm, gp) do {                                                     \
    unsigned long long _g;                                                    \
    asm("cvta.to.global.u64 %0, %1;" : "=l"(_g) : "l"(gp));                   \
    asm volatile("cp.async.cg.shared.global [%0], [%1], 16;" :: "r"(sm), "l"(_g)); \
} while (0)
#define CP_COMMIT() asm volatile("cp.async.commit_group;" ::: "memory")
#define CP_WAIT(n)  asm volatile("cp.async.wait_group %0;" :: "n"(n) : "memory")

// async load of one 128x128 fp16 plane
__device__ __forceinline__ void cpa_tile1(const ushort* __restrict__ gp,
                                          int row0, int col0, int ldg,
                                          uint sbase, int tid) {
#pragma unroll
    for (int i = 0; i < 8; i++) {
        int idx = tid + 256 * i;
        int r = idx >> 4, g = idx & 15;
        CP16(sbase + r * LDT_B + g * 16, gp + (size_t)(row0 + r) * ldg + col0 + g * 8);
    }
}

// ---------------------------------------------------------------------------
// full-N MMA: warp tile 16(M) x 128(N), single-pass fp16.
// B fragments depth-2 pipelined.
// ---------------------------------------------------------------------------
__device__ __forceinline__ void ldfragB(uint bP, uint offB, int it, uint f[8]) {
    int ks = it >> 2, pp = it & 3;
    uint ob0 = offB + (uint)((2 * pp) * 16 * LDT_B) + (uint)(ks * 32);
    uint ob1 = ob0 + 16 * LDT_B;
    ldsm4(f + 0, bP + ob0);
    ldsm4(f + 4, bP + ob1);
}

__device__ __forceinline__ void mma_fullN(const uint aH[8][4],
                                          uint bP, uint offB,
                                          float acc[16][4]) {
    uint f[2][8];
    ldfragB(bP, offB, 0, f[0]);
#pragma unroll
    for (int it = 0; it < 32; it++) {
        if (it < 31) ldfragB(bP, offB, it + 1, f[(it + 1) & 1]);
        const uint* F = f[it & 1];
        int ks = it >> 2, pp = it & 3;
        mma_f16(acc[4 * pp + 0], aH[ks], &F[0]);
        mma_f16(acc[4 * pp + 1], aH[ks], &F[2]);
        mma_f16(acc[4 * pp + 2], aH[ks], &F[4]);
        mma_f16(acc[4 * pp + 3], aH[ks], &F[6]);
    }
}

// ---------------------------------------------------------------------------
// K0: degree -> inv_sqrt_deg
// ---------------------------------------------------------------------------
__global__ void deg_kernel(const int* __restrict__ dst) {
    int g = blockIdx.x * blockDim.x + threadIdx.x;
    if (g >= BGR) return;
    int base = g * NPG;
    int cnt[NPG];
#pragma unroll
    for (int j = 0; j < NPG; j++) cnt[j] = 1;
#pragma unroll
    for (int e = 0; e < EPG; e++) {
        int dl = dst[g * EPG + e] - base;
#pragma unroll
        for (int j = 0; j < NPG; j++) cnt[j] += (dl == j) ? 1 : 0;
    }
#pragma unroll
    for (int j = 0; j < NPG; j++)
        g_inv[base + j] = rsqrtf((float)cnt[j]);
}

// ---------------------------------------------------------------------------
// K1: embedding -> fp16 h plane
// ---------------------------------------------------------------------------
__global__ void embed_kernel(const float4* __restrict__ opt,
                             const float4* __restrict__ de,
                             const int* __restrict__ op_idx) {
    int idx = blockIdx.x * blockDim.x + threadIdx.x;   // NNODE*32
    int n = idx >> 5, c = idx & 31;
    float4 t = opt[op_idx[n] * 32 + c];
    float4 d = de[c];
    uint u0 = pk2f16(t.x + d.x, t.y + d.y);
    uint u1 = pk2f16(t.z + d.z, t.w + d.w);
    *reinterpret_cast<uint2*>(g_hh + (size_t)n * DM + 4 * c) = make_uint2(u0, u1);
}

// ---------------------------------------------------------------------------
// K2: per-graph aggregation — WARP PER GRAPH, lane owns 4 cols (uint2).
// Warp-uniform edge predicates; accumulation order identical to prior
// version (self term, then edges in index order) -> bit-identical output.
// ---------------------------------------------------------------------------
__global__ __launch_bounds__(256) void agg_kernel(const int* __restrict__ src,
                                                  const int* __restrict__ dst) {
    __shared__ ushort hsm[8][NPG * DM];     // 8 graphs x 1152 fp16 = 18432 B
    __shared__ float  sinv[8][12];

    int wid = threadIdx.x >> 5, lane = threadIdx.x & 31;
    int g = blockIdx.x * 8 + wid;
    int nbase = g * NPG;

    // load h rows (coalesced uint2) -> registers + warp-private smem strip
    uint2 hrow[NPG];
#pragma unroll
    for (int j = 0; j < NPG; j++) {
        hrow[j] = *reinterpret_cast<const uint2*>(g_hh + (size_t)(nbase + j) * DM + lane * 4);
        *reinterpret_cast<uint2*>(&hsm[wid][j * DM + lane * 4]) = hrow[j];
    }
    if (lane < NPG) sinv[wid][lane] = g_inv[nbase + lane];

    // edges: each lane loads all 16 (L1 broadcast); kept in unrolled regs
    int sl[EPG], dl[EPG];
#pragma unroll
    for (int e = 0; e < EPG; e++) {
        sl[e] = src[g * EPG + e] - nbase;
        dl[e] = dst[g * EPG + e] - nbase;
    }
    __syncwarp();

#pragma unroll
    for (int j = 0; j < NPG; j++) {
        float iv = sinv[wid][j];
        float w0 = iv * iv;
        float a0 = w0 * f16f(hrow[j].x & 0xffffu);
        float a1 = w0 * f16f(hrow[j].x >> 16);
        float a2 = w0 * f16f(hrow[j].y & 0xffffu);
        float a3 = w0 * f16f(hrow[j].y >> 16);
#pragma unroll
        for (int e = 0; e < EPG; e++) {
            if (dl[e] == j) {               // warp-uniform predicate
                float w = sinv[wid][sl[e]] * iv;
                uint2 hv = *reinterpret_cast<const uint2*>(&hsm[wid][sl[e] * DM + lane * 4]);
                a0 += w * f16f(hv.x & 0xffffu);
                a1 += w * f16f(hv.x >> 16);
                a2 += w * f16f(hv.y & 0xffffu);
                a3 += w * f16f(hv.y >> 16);
            }
        }
        uint2 o = make_uint2(pk2f16(a0, a1), pk2f16(a2, a3));
        *reinterpret_cast<uint2*>(g_agh + (size_t)(nbase + j) * DM + lane * 4) = o;
    }
}

// ---------------------------------------------------------------------------
// Weight prep: plane[c][r] = fp16(src[r][c])
// ---------------------------------------------------------------------------
__global__ void prep_w(const float* __restrict__ src,
                       ushort* __restrict__ dh, int R, int C) {
    int l = blockIdx.z;
    src += (size_t)l * R * C;
    dh  += (size_t)l * R * C;
    int n = blockIdx.x * blockDim.x + threadIdx.x;
    if (n >= R * C) return;
    int c = n / R, r = n % R;
    dh[n] = (ushort)(pk2f16(src[(size_t)r * C + c], 0.f) & 0xffffu);
}

// ---------------------------------------------------------------------------
// K3: fused layer GEMMs, register-resident intermediates, fp16 single-pass.
// ---------------------------------------------------------------------------
__global__ __launch_bounds__(256) void layer_mm(
    const ushort* __restrict__ Wgh,
    const ushort* __restrict__ W1h,
    const ushort* __restrict__ W2h,
    const float* __restrict__ bg, const float* __restrict__ lng,
    const float* __restrict__ lnb, const float* __restrict__ b1,
    const float* __restrict__ b2) {

    extern __shared__ char dsm[];
    __shared__ __align__(16) float sBg[DM], sLng[DM], sLnb[DM], sB1[DFF], sB2[DM];

    int tid = threadIdx.x, lane = tid & 31, wid = tid >> 5;
    int gid = lane >> 2, tig = lane & 3;
    int colb = 2 * tig;
    uint sb = smem_u32(dsm);
    int m0 = blockIdx.x * 128;

    // async: agg -> P, Wg -> Q (G1); W1_0 -> R (G2)
    cpa_tile1(g_agh + (size_t)m0 * DM, 0, 0, DM, sb + P_O, tid);
    cpa_tile1(Wgh, 0, 0, DM, sb + Q_O, tid);
    CP_COMMIT();
    cpa_tile1(W1h, 0, 0, DM, sb + R_O, tid);
    CP_COMMIT();

    if (tid < DM) { sBg[tid] = bg[tid]; sLng[tid] = lng[tid]; sLnb[tid] = lnb[tid]; sB2[tid] = b2[tid]; }
    for (int i = tid; i < DFF; i += 256) sB1[i] = b1[i];

    uint offA = (uint)((wid * 16 + (lane & 15)) * LDT_B + ((lane >> 4) << 4));
    uint offB = (uint)(((lane & 7) + ((lane >> 4) << 3)) * LDT_B + (((lane >> 3) & 1) << 4));

    // ---- GCN: acc = agg @ Wg --------------------------------------------
    uint hAh[8][4];
    float acc[16][4];
#pragma unroll
    for (int i = 0; i < 16; i++) { acc[i][0] = acc[i][1] = acc[i][2] = acc[i][3] = 0.f; }

    CP_WAIT(1);
    __syncthreads();
#pragma unroll
    for (int ks = 0; ks < 8; ks++)
        ldsm4(hAh[ks], sb + P_O + offA + ks * 32);
    mma_fullN(hAh, sb + Q_O, offB, acc);

    // ---- bias + relu + LayerNorm entirely in registers ------------------
    float s0 = 0.f, s1 = 0.f, q0 = 0.f, q1 = 0.f;
#pragma unroll
    for (int in = 0; in < 16; in++) {
        float2 bb = *reinterpret_cast<const float2*>(&sBg[in * 8 + colb]);
        float v;
        v = fmaxf(acc[in][0] + bb.x, 0.f); acc[in][0] = v; s0 += v; q0 += v * v;
        v = fmaxf(acc[in][1] + bb.y, 0.f); acc[in][1] = v; s0 += v; q0 += v * v;
        v = fmaxf(acc[in][2] + bb.x, 0.f); acc[in][2] = v; s1 += v; q1 += v * v;
        v = fmaxf(acc[in][3] + bb.y, 0.f); acc[in][3] = v; s1 += v; q1 += v * v;
    }
    s0 += __shfl_xor_sync(0xffffffffu, s0, 1); s0 += __shfl_xor_sync(0xffffffffu, s0, 2);
    s1 += __shfl_xor_sync(0xffffffffu, s1, 1); s1 += __shfl_xor_sync(0xffffffffu, s1, 2);
    q0 += __shfl_xor_sync(0xffffffffu, q0, 1); q0 += __shfl_xor_sync(0xffffffffu, q0, 2);
    q1 += __shfl_xor_sync(0xffffffffu, q1, 1); q1 += __shfl_xor_sync(0xffffffffu, q1, 2);
    float mu0 = s0 * (1.f / 128.f), mu1 = s1 * (1.f / 128.f);
    float rs0 = rsqrtf(fmaxf(q0 * (1.f / 128.f) - mu0 * mu0, 0.f) + 1e-5f);
    float rs1 = rsqrtf(fmaxf(q1 * (1.f / 128.f) - mu1 * mu1, 0.f) + 1e-5f);

#pragma unroll
    for (int ks = 0; ks < 8; ks++) {
        int in0 = 2 * ks, in1 = 2 * ks + 1;
        float2 g0 = *reinterpret_cast<const float2*>(&sLng[in0 * 8 + colb]);
        float2 c0 = *reinterpret_cast<const float2*>(&sLnb[in0 * 8 + colb]);
        float2 g1 = *reinterpret_cast<const float2*>(&sLng[in1 * 8 + colb]);
        float2 c1 = *reinterpret_cast<const float2*>(&sLnb[in1 * 8 + colb]);
        hAh[ks][0] = pk2f16((acc[in0][0] - mu0) * rs0 * g0.x + c0.x,
                            (acc[in0][1] - mu0) * rs0 * g0.y + c0.y);
        hAh[ks][1] = pk2f16((acc[in0][2] - mu1) * rs1 * g0.x + c0.x,
                            (acc[in0][3] - mu1) * rs1 * g0.y + c0.y);
        hAh[ks][2] = pk2f16((acc[in1][0] - mu0) * rs0 * g1.x + c1.x,
                            (acc[in1][1] - mu0) * rs0 * g1.y + c1.y);
        hAh[ks][3] = pk2f16((acc[in1][2] - mu1) * rs1 * g1.x + c1.x,
                            (acc[in1][3] - mu1) * rs1 * g1.y + c1.y);
    }

    // ---- FFN loop: mid stays in registers -------------------------------
    float acc2[16][4];
#pragma unroll
    for (int i = 0; i < 16; i++) { acc2[i][0] = acc2[i][1] = acc2[i][2] = acc2[i][3] = 0.f; }

    for (int c = 0; c < 4; c++) {
        __syncthreads();                           // Q released
        cpa_tile1(W2h, 0, c * 128, DFF, sb + Q_O, tid);
        CP_COMMIT();
        CP_WAIT(1);                                // W1c resident in R
        __syncthreads();

        float acc1[16][4];
#pragma unroll
        for (int i = 0; i < 16; i++) { acc1[i][0] = acc1[i][1] = acc1[i][2] = acc1[i][3] = 0.f; }
        mma_fullN(hAh, sb + R_O, offB, acc1);

        // bias + relu -> mid A-fragments (registers only)
        uint mAh[8][4];
#pragma unroll
        for (int ks = 0; ks < 8; ks++) {
            int in0 = 2 * ks, in1 = 2 * ks + 1;
            float2 b0 = *reinterpret_cast<const float2*>(&sB1[c * 128 + in0 * 8 + colb]);
            float2 b1v = *reinterpret_cast<const float2*>(&sB1[c * 128 + in1 * 8 + colb]);
            mAh[ks][0] = pk2f16(fmaxf(acc1[in0][0] + b0.x, 0.f),
                                fmaxf(acc1[in0][1] + b0.y, 0.f));
            mAh[ks][1] = pk2f16(fmaxf(acc1[in0][2] + b0.x, 0.f),
                                fmaxf(acc1[in0][3] + b0.y, 0.f));
            mAh[ks][2] = pk2f16(fmaxf(acc1[in1][0] + b1v.x, 0.f),
                                fmaxf(acc1[in1][1] + b1v.y, 0.f));
            mAh[ks][3] = pk2f16(fmaxf(acc1[in1][2] + b1v.x, 0.f),
                                fmaxf(acc1[in1][3] + b1v.y, 0.f));
        }

        CP_WAIT(0);                                // W2c resident in Q
        __syncthreads();                           // all warps done with R
        if (c < 3) {
            cpa_tile1(W1h, (c + 1) * 128, 0, DM, sb + R_O, tid);
            CP_COMMIT();
        }
        mma_fullN(mAh, sb + Q_O, offB, acc2);
    }

    // ---- epilogue: h_out = hLN + ffn + b2, straight from registers ------
    int row0 = m0 + wid * 16 + gid, row1 = row0 + 8;
#pragma unroll
    for (int in = 0; in < 16; in++) {
        int col = in * 8 + colb;
        float2 b2v = *reinterpret_cast<const float2*>(&sB2[col]);
        int ks = in >> 1, jb = (in & 1) * 2;
        uint r0 = hAh[ks][jb], r1 = hAh[ks][jb + 1];
        float v0 = acc2[in][0] + b2v.x + f16f(r0 & 0xffffu);
        float v1 = acc2[in][1] + b2v.y + f16f(r0 >> 16);
        *reinterpret_cast<uint*>(g_hh + (size_t)row0 * DM + col) = pk2f16(v0, v1);
        v0 = acc2[in][2] + b2v.x + f16f(r1 & 0xffffu);
        v1 = acc2[in][3] + b2v.y + f16f(r1 >> 16);
        *reinterpret_cast<uint*>(g_hh + (size_t)row1 * DM + col) = pk2f16(v0, v1);
    }
}

// ---------------------------------------------------------------------------
// K6: readout
// ---------------------------------------------------------------------------
__global__ __launch_bounds__(128) void readout_kernel(const float4* __restrict__ fcw,
                                                      const float* __restrict__ fcb,
                                                      float* __restrict__ out) {
    int w = threadIdx.x >> 5, lane = threadIdx.x & 31;
    int g = blockIdx.x * 4 + w;
    size_t base = (size_t)g * NPG * DM + 4 * lane;
    float4 s = make_float4(0.f, 0.f, 0.f, 0.f);
#pragma unroll
    for (int j = 0; j < NPG; j++) {
        ushort4 hv = *reinterpret_cast<const ushort4*>(g_hh + base + j * DM);
        s.x += f16f(hv.x); s.y += f16f(hv.y); s.z += f16f(hv.z); s.w += f16f(hv.w);
    }
    float4 wv = fcw[lane];
    float p = s.x * wv.x + s.y * wv.y + s.z * wv.z + s.w * wv.w;
#pragma unroll
    for (int o = 16; o; o >>= 1) p += __shfl_xor_sync(0xffffffffu, p, o);
    if (lane == 0)
        out[g] = 1.f / (1.f + expf(-(p * (1.f / 9.f) + fcb[0])));
}

// ---------------------------------------------------------------------------
// Launcher
// ---------------------------------------------------------------------------
extern "C" void kernel_launch(void* const* d_in, const int* in_sizes, int n_in,
                              void* d_out, int out_size) {
    const float* op_table   = (const float*)d_in[0];
    const float* device_emb = (const float*)d_in[1];
    const float* Wg         = (const float*)d_in[2];
    const float* bg         = (const float*)d_in[3];
    const float* ln_g       = (const float*)d_in[4];
    const float* ln_b       = (const float*)d_in[5];
    const float* W1         = (const float*)d_in[6];
    const float* b1         = (const float*)d_in[7];
    const float* W2         = (const float*)d_in[8];
    const float* b2         = (const float*)d_in[9];
    const float* fc_w       = (const float*)d_in[10];
    const float* fc_b       = (const float*)d_in[11];
    const int*   op_idx     = (const int*)d_in[12];
    const int*   src        = (const int*)d_in[13];
    const int*   dst        = (const int*)d_in[14];
    float* out = (float*)d_out;

    cudaFuncSetAttribute(layer_mm, cudaFuncAttributeMaxDynamicSharedMemorySize, LM_SMEM);

    ushort *wgh, *w1h, *w2h;
    cudaGetSymbolAddress((void**)&wgh, g_Wgh);
    cudaGetSymbolAddress((void**)&w1h, g_W1h);
    cudaGetSymbolAddress((void**)&w2h, g_W2h);

    prep_w<<<dim3((DM * DM + 255) / 256, 1, NL), 256>>>(Wg, wgh, DM, DM);
    prep_w<<<dim3((DM * DFF + 255) / 256, 1, NL), 256>>>(W1, w1h, DM, DFF);
    prep_w<<<dim3((DM * DFF + 255) / 256, 1, NL), 256>>>(W2, w2h, DFF, DM);

    deg_kernel<<<BGR / 256, 256>>>(dst);
    embed_kernel<<<(NNODE * 32) / 256, 256>>>(
        (const float4*)op_table, (const float4*)device_emb, op_idx);

    for (int l = 0; l < NL; l++) {
        size_t o1 = (size_t)l * DM * DM, o2 = (size_t)l * DFF * DM, o3 = (size_t)l * DM * DFF;
        agg_kernel<<<BGR / 8, 256>>>(src, dst);
        layer_mm<<<NTILES, 256, LM_SMEM>>>(
            wgh + o1, w1h + o2, w2h + o3,
            bg + l * DM, ln_g + l * DM, ln_b + l * DM, b1 + l * DFF, b2 + l * DM);
    }

    readout_kernel<<<BGR / 4, 128>>>((const float4*)fc_w, fc_b, out);
}